// round 13
// baseline (speedup 1.0000x reference)
#include <cuda_runtime.h>
#include <cuda_bf16.h>
#include <mma.h>
#include <math.h>

using namespace nvcuda;

#define N_SRC   16384
#define N_DST   8192

// ---------------- scratch (device globals; no allocations) ----------------
__device__ float g_proj[(long)N_SRC * 1536];   // [0:512) node_k | [512:1024) node_v | [1024:1536) qh
__device__ float g_biasq[512];
__device__ float g_cosph[128];
__device__ float g_wfold[(long)N_DST * 1536];
__device__ float g_ctx[(long)N_DST * 512];
__device__ float g_x[(long)N_DST * 320];
// bf16-split operands, COMPACT 2-segment storage: [hi|lo]
// (GEMM loader remaps logical 3-segment K: A [hi|lo|hi]: seg2->seg0; B [hi|hi|lo]: seg1->seg0, seg2->seg1)
__device__ __nv_bfloat16 g_A3[(long)N_SRC * 256];
__device__ __nv_bfloat16 g_B3[(long)1536 * 256];
__device__ __nv_bfloat16 g_qh3[(long)N_DST * 1024];    // per n: 8 heads x [hi64|lo64]
__device__ __nv_bfloat16 g_wk3[8 * 192 * 128];
__device__ __nv_bfloat16 g_et3[(long)N_DST * 3072];    // per n: 8 heads x [hi192|lo192]
__device__ __nv_bfloat16 g_wv3[8 * 64 * 384];
__device__ __nv_bfloat16 g_ctx3[(long)N_DST * 1024];
__device__ __nv_bfloat16 g_fcw3[(long)320 * 1024];
__device__ __nv_bfloat16 g_hcat3[(long)N_DST * 896];
__device__ __nv_bfloat16 g_nodew3[(long)128 * 896];

// ---------------- helpers ----------------
__device__ __forceinline__ unsigned long long pack2(float x, float y) {
    unsigned long long r;
    asm("mov.b64 %0, {%1, %2};" : "=l"(r) : "f"(x), "f"(y));
    return r;
}
__device__ __forceinline__ void unpack2(unsigned long long v, float& x, float& y) {
    asm("mov.b64 {%0, %1}, %2;" : "=f"(x), "=f"(y) : "l"(v));
}
__device__ __forceinline__ void ffma2(unsigned long long& d, unsigned long long a, unsigned long long b) {
    asm("fma.rn.f32x2 %0, %1, %2, %0;" : "+l"(d) : "l"(a), "l"(b));
}
__device__ __forceinline__ __nv_bfloat16 bsplit(float v, int is_lo) {
    __nv_bfloat16 h = __float2bfloat16(v);
    if (!is_lo) return h;
    return __float2bfloat16(v - __bfloat162float(h));
}
__device__ __forceinline__ unsigned int bf2pack(float a, float b) {
    __nv_bfloat162 t;
    t.x = __float2bfloat16(a);
    t.y = __float2bfloat16(b);
    return *(unsigned int*)&t;
}
__device__ __forceinline__ void cp16(unsigned int saddr, const void* gptr) {
    asm volatile("cp.async.cg.shared.global [%0], [%1], 16;" :: "r"(saddr), "l"(gptr) : "memory");
}
__device__ __forceinline__ void cp_commit() {
    asm volatile("cp.async.commit_group;" ::: "memory");
}
template<int N>
__device__ __forceinline__ void cp_wait() {
    asm volatile("cp.async.wait_group %0;" :: "n"(N) : "memory");
}

// ---------------- prep: compact weight splits + biasq + cosph ----------------
__global__ void prep_kernel(const float* __restrict__ wks, const float* __restrict__ wvs,
                            const float* __restrict__ wqs, const float* __restrict__ fcw,
                            const float* __restrict__ nw,  const float* __restrict__ ph)
{
    const int S0 = 393216;             // B3: 1536 x 256
    const int S1 = S0 + 196608;        // wk3: 8 x 192 x 128
    const int S2 = S1 + 196608;        // wv3: 8 x 64 x 384
    const int S3 = S2 + 327680;        // fcw3: 320 x 1024
    const int S4 = S3 + 114688;        // nodew3: 128 x 896
    const int S5 = S4 + 512;           // biasq
    const int S6 = S5 + 128;           // cosph
    int t = blockIdx.x * blockDim.x + threadIdx.x;
    if (t < S0) {
        int r = t / 256, kp = t % 256;
        int k = kp & 127, seg = kp >> 7;
        float v;
        if (r < 512)       v = wks[r * 320 + k];
        else if (r < 1024) v = wvs[(r - 512) * 320 + k];
        else               v = wqs[(r - 1024) * 320 + k];
        g_B3[t] = bsplit(v, seg);
    } else if (t < S1) {
        int i = t - S0;
        int h = i / 24576, rem = i % 24576;
        int c = rem / 128, kp = rem % 128;
        int d = kp & 63, seg = kp >> 6;
        float v = wks[(h * 64 + d) * 320 + 128 + c];
        g_wk3[i] = bsplit(v, seg);
    } else if (t < S2) {
        int i = t - S1;
        int h = i / 24576, rem = i % 24576;
        int d = rem / 384, kp = rem % 384;
        int c = kp % 192, seg = kp / 192;
        float v = wvs[(h * 64 + d) * 320 + 128 + c];
        g_wv3[i] = bsplit(v, seg);
    } else if (t < S3) {
        int i = t - S2;
        int c = i / 1024, kp = i % 1024;
        int j = kp & 511, seg = kp >> 9;
        float v = fcw[c * 512 + j];
        g_fcw3[i] = bsplit(v, seg);
    } else if (t < S4) {
        int i = t - S3;
        int o = i / 896, kp = i % 896;
        int c = kp % 448, seg = kp / 448;
        float v = nw[o * 448 + c];
        g_nodew3[i] = bsplit(v, seg);
    } else if (t < S5) {
        int j = t - S4;
        float acc = 0.f;
        for (int d = 0; d < 128; d++) acc += cosf(ph[d]) * wqs[j * 320 + 192 + d];
        g_biasq[j] = acc;
    } else if (t < S6) {
        g_cosph[t - S5] = cosf(ph[t - S5]);
    }
}

// ---------------- conversion ----------------
__global__ void convA_kernel(const float* __restrict__ nf) {
    int i = blockIdx.x * 256 + threadIdx.x;
    if (i < N_SRC * 128) {
        int m = i >> 7, k = i & 127;
        float v = nf[i];
        __nv_bfloat16 hi = __float2bfloat16(v);
        __nv_bfloat16 lo = __float2bfloat16(v - __bfloat162float(hi));
        long b = (long)m * 256;
        g_A3[b + k] = hi;
        g_A3[b + 128 + k] = lo;
    }
}

// ---------------- bf16 wmma GEMM, BK=64, cp.async pipeline, compact-split remap -----
// Logical K3 = 3*SEG; A stored [hi|lo]: k0>=2*SEG -> k0-2*SEG
//                     B stored [hi|lo]: k0>=SEG   -> k0-SEG
// EPI: 0 plain store;
//      2 accumulate(init from C) -> write bf16 [hi|lo] to aux_bf (ctx3 layout);
//      3 relu(v + aux_f[col]) -> store to C;
//      4 qh tiles (tn0>=1024 && tm0<N_DST): stage via shared, add aux_f bias,
//        write C AND compact qh3 to aux_bf; other tiles: plain frag store.
template<int BM, int BN, int EPI, int SEG>
__global__ void __launch_bounds__(256, 3)
wmma_gemm(const __nv_bfloat16* __restrict__ A,
          const __nv_bfloat16* __restrict__ Bt,
          float* __restrict__ C,
          int K3, int lda, int ldb, int ldc,
          long bsA, long bsB, long bsC,
          const float* __restrict__ aux_f,
          __nv_bfloat16* __restrict__ aux_bf)
{
    constexpr int BK = 64;
    constexpr int PAD = 8;
    constexpr int LDSH = BK + PAD;
    constexpr int CPR = BK / 8;
    constexpr int FR_M = BM / 64;
    constexpr int FR_N = BN / 32;
    constexpr int A_LD = BM * CPR / 256;
    constexpr int B_LD = BN * CPR / 256;
    __shared__ __align__(16) __nv_bfloat16 sbuf[2][(BM + BN) * LDSH];
    static_assert(sizeof(sbuf) >= BM * BN * sizeof(float), "sC alias too small");
    const int bz = blockIdx.z;
    A += (long)bz * bsA; Bt += (long)bz * bsB; C += (long)bz * bsC;
    const int tid = threadIdx.x;
    const int wid = tid >> 5;
    const int wm = wid & 3;
    const int wn = wid >> 2;
    const int tm0 = blockIdx.y * BM;
    const int tn0 = blockIdx.x * BN;

    wmma::fragment<wmma::accumulator, 16, 16, 16, float> cf[FR_M][FR_N];
#pragma unroll
    for (int i = 0; i < FR_M; i++)
#pragma unroll
        for (int j = 0; j < FR_N; j++) {
            if (EPI == 2)
                wmma::load_matrix_sync(cf[i][j],
                    &C[(long)(tm0 + wm * 32 + i * 16) * ldc + tn0 + wn * (BN / 2) + j * 16],
                    ldc, wmma::mem_row_major);
            else
                wmma::fill_fragment(cf[i][j], 0.f);
        }

    auto loadStage = [&](int st, int k0) {
        int ka = (k0 >= 2 * SEG) ? k0 - 2 * SEG : k0;   // A: seg2 aliases seg0
        int kb = (k0 >= SEG)     ? k0 - SEG     : k0;   // B: seg1 aliases seg0
#pragma unroll
        for (int it = 0; it < A_LD; it++) {
            int idx = tid + it * 256;
            int r = idx / CPR, c8 = idx % CPR;
            cp16((unsigned int)__cvta_generic_to_shared(&sbuf[st][r * LDSH + c8 * 8]),
                 &A[(long)(tm0 + r) * lda + ka + c8 * 8]);
        }
#pragma unroll
        for (int it = 0; it < B_LD; it++) {
            int idx = tid + it * 256;
            int r = idx / CPR, c8 = idx % CPR;
            cp16((unsigned int)__cvta_generic_to_shared(&sbuf[st][(BM + r) * LDSH + c8 * 8]),
                 &Bt[(long)(tn0 + r) * ldb + kb + c8 * 8]);
        }
        cp_commit();
    };

    const int nIter = K3 / BK;
    loadStage(0, 0);
    for (int it = 0; it < nIter; it++) {
        int st = it & 1;
        if (it + 1 < nIter) {
            loadStage(st ^ 1, (it + 1) * BK);
            cp_wait<1>();
        } else {
            cp_wait<0>();
        }
        __syncthreads();
#pragma unroll
        for (int kk = 0; kk < BK; kk += 16) {
            wmma::fragment<wmma::matrix_a, 16, 16, 16, __nv_bfloat16, wmma::row_major> af[FR_M];
            wmma::fragment<wmma::matrix_b, 16, 16, 16, __nv_bfloat16, wmma::col_major> bf[FR_N];
#pragma unroll
            for (int i = 0; i < FR_M; i++)
                wmma::load_matrix_sync(af[i], &sbuf[st][(wm * 32 + i * 16) * LDSH + kk], LDSH);
#pragma unroll
            for (int j = 0; j < FR_N; j++)
                wmma::load_matrix_sync(bf[j], &sbuf[st][(BM + wn * (BN / 2) + j * 16) * LDSH + kk], LDSH);
#pragma unroll
            for (int i = 0; i < FR_M; i++)
#pragma unroll
                for (int j = 0; j < FR_N; j++)
                    wmma::mma_sync(cf[i][j], af[i], bf[j], cf[i][j]);
        }
        __syncthreads();
    }

    bool qh_tile = (EPI == 4) && (tn0 >= 1024) && (tm0 < N_DST);

    if ((EPI == 0) || (EPI == 4 && !qh_tile)) {
#pragma unroll
        for (int i = 0; i < FR_M; i++)
#pragma unroll
            for (int j = 0; j < FR_N; j++)
                wmma::store_matrix_sync(&C[(long)(tm0 + wm * 32 + i * 16) * ldc + tn0 + wn * (BN / 2) + j * 16],
                                        cf[i][j], ldc, wmma::mem_row_major);
    } else {
        // stage fp32 tile in shared (aliasing the dead pipeline buffers)
        float* sC = (float*)&sbuf[0][0];
#pragma unroll
        for (int i = 0; i < FR_M; i++)
#pragma unroll
            for (int j = 0; j < FR_N; j++)
                wmma::store_matrix_sync(&sC[(wm * 32 + i * 16) * BN + wn * (BN / 2) + j * 16],
                                        cf[i][j], BN, wmma::mem_row_major);
        __syncthreads();
        for (int idx = tid; idx < BM * BN; idx += 256) {
            int r = idx / BN, c = idx % BN;
            float v = sC[idx];
            int row = tm0 + r;
            if (EPI == 2) {
                int j = bz * 64 + tn0 + c;
                __nv_bfloat16 hi = __float2bfloat16(v);
                __nv_bfloat16 lo = __float2bfloat16(v - __bfloat162float(hi));
                long b = (long)row * 1024 + j;
                aux_bf[b] = hi;
                aux_bf[b + 512] = lo;
            }
            if (EPI == 3) {
                int col = tn0 + c;
                C[(long)row * ldc + col] = fmaxf(v + aux_f[col], 0.f);
            }
            if (EPI == 4) {
                int col = tn0 + c;
                int j = col - 1024;                  // qh-local 0..511
                v += aux_f[j];
                C[(long)row * ldc + col] = v;
                int h = j >> 6, d = j & 63;
                __nv_bfloat16 hi = __float2bfloat16(v);
                __nv_bfloat16 lo = __float2bfloat16(v - __bfloat162float(hi));
                long b = (long)row * 1024 + h * 128;
                aux_bf[b + d] = hi;
                aux_bf[b + 64 + d] = lo;
            }
        }
    }
}

// ---------------- fused attention kernel (round-9 body, compact et3 write) ----------
__global__ void attn_kernel(const float* __restrict__ ef, const float* __restrict__ dt,
                            const int* __restrict__ nidx,
                            const float* __restrict__ freq, const float* __restrict__ ph)
{
    const int n = blockIdx.x;
    const int tid = threadIdx.x;
    __shared__ __align__(16) float s_qh[512];
    __shared__ __align__(16) float s_wf[1536];
    __shared__ __align__(16) float s_te[32][132];
    __shared__ __align__(16) float s_e[32][68];
    __shared__ float s_dt[32];
    __shared__ int   s_idx[16];
    __shared__ float s_fr[128], s_ph[128];
    __shared__ float s_at[8][33];
    __shared__ float s_a2[8][17];
    __shared__ float s_ns[8][17];

    for (int i = tid; i < 512;  i += 256) s_qh[i] = g_proj[(long)n * 1536 + 1024 + i];
    for (int i = tid; i < 1536; i += 256) s_wf[i] = g_wfold[(long)n * 1536 + i];
    {
        const float4* ef4 = (const float4*)(ef + (long)n * 2048);
        for (int i = tid; i < 512; i += 256) {
            int l = i >> 4, c4 = i & 15;
            *(float4*)&s_e[l][c4 * 4] = ef4[i];
        }
    }
    if (tid < 128) { s_fr[tid] = freq[tid]; s_ph[tid] = ph[tid]; }
    if (tid < 32)  s_dt[tid] = dt[(long)n * 32 + tid];
    if (tid < 16)  s_idx[tid] = nidx[n * 16 + tid];
    __syncthreads();

    // temporal encoding via hardware cos (MUFU pipe)
    for (int i = tid; i < 4096; i += 256) {
        int l = i >> 7, d = i & 127;
        s_te[l][d] = __cosf(fmaf(s_dt[l], s_fr[d], s_ph[d]));
    }
    __syncthreads();

    const int h = tid >> 5, l = tid & 31;

    // node scores (16 distinct neighbors, coalesced)
    {
#pragma unroll
        for (int jb = 0; jb < 16; jb += 4) {
            int j = jb + (l >> 3);
            int d0 = (l & 7) * 8;
            const float4* p = (const float4*)(g_proj + (long)s_idx[j] * 1536 + h * 64 + d0);
            const float4* q = (const float4*)(s_qh + h * 64 + d0);
            float4 x0 = p[0], x1 = p[1];
            float4 q0 = q[0], q1 = q[1];
            float d = x0.x * q0.x + x0.y * q0.y + x0.z * q0.z + x0.w * q0.w
                    + x1.x * q1.x + x1.y * q1.y + x1.z * q1.z + x1.w * q1.w;
            d += __shfl_xor_sync(0xffffffffu, d, 1);
            d += __shfl_xor_sync(0xffffffffu, d, 2);
            d += __shfl_xor_sync(0xffffffffu, d, 4);
            if ((l & 7) == 0) s_ns[h][j] = d;
        }
        __syncwarp();
    }

    // scores + softmax
    {
        float sc = s_ns[h][l >> 1];
        const float4* ev = (const float4*)(&s_e[l][0]);
        const float4* we = (const float4*)(s_wf + h * 192);
#pragma unroll
        for (int j = 0; j < 16; j++) {
            float4 a = ev[j], b = we[j];
            sc += a.x * b.x + a.y * b.y + a.z * b.z + a.w * b.w;
        }
        const float4* tv = (const float4*)(&s_te[l][0]);
        const float4* wt = (const float4*)(s_wf + h * 192 + 64);
#pragma unroll
        for (int j = 0; j < 32; j++) {
            float4 a = tv[j], b = wt[j];
            sc += a.x * b.x + a.y * b.y + a.z * b.z + a.w * b.w;
        }
        sc *= 0.125f;
        float mx = sc;
        for (int o = 16; o; o >>= 1) mx = fmaxf(mx, __shfl_xor_sync(0xffffffffu, mx, o));
        float ex = expf(sc - mx);
        float sm = ex;
        for (int o = 16; o; o >>= 1) sm += __shfl_xor_sync(0xffffffffu, sm, o);
        float p = ex / sm;
        s_at[h][l] = p;
        float pp = p + __shfl_xor_sync(0xffffffffu, p, 1);
        if ((l & 1) == 0) s_a2[h][l >> 1] = pp;
    }
    __syncthreads();

    // ctx node part (fp32, consumed as accumulator-init by wmma5)
    {
        int j = tid * 2;
        int hh = j >> 6;
        unsigned long long acc = 0ull;
#pragma unroll 4
        for (int r = 0; r < 16; r++) {
            float2 v = *(const float2*)&g_proj[(long)s_idx[r] * 1536 + 512 + j];
            float a = s_a2[hh][r];
            ffma2(acc, pack2(a, a), pack2(v.x, v.y));
        }
        float o0, o1;
        unpack2(acc, o0, o1);
        *(float2*)&g_ctx[(long)n * 512 + j] = make_float2(o0, o1);
    }
    // ebar / tbar, float4 -> bf16 [hi192|lo192] per head (compact)
    for (int p = tid; p < 384; p += 256) {
        int hh = p / 48, c4 = (p % 48) * 4;
        unsigned long long acc0 = 0ull, acc1 = 0ull;
        if (c4 < 64) {
#pragma unroll
            for (int ll = 0; ll < 32; ll++) {
                float4 e = *(const float4*)&s_e[ll][c4];
                float a = s_at[hh][ll];
                unsigned long long a2 = pack2(a, a);
                ffma2(acc0, a2, pack2(e.x, e.y));
                ffma2(acc1, a2, pack2(e.z, e.w));
            }
        } else {
            int d = c4 - 64;
#pragma unroll
            for (int ll = 0; ll < 32; ll++) {
                float4 t4 = *(const float4*)&s_te[ll][d];
                float a = s_at[hh][ll];
                unsigned long long a2 = pack2(a, a);
                ffma2(acc0, a2, pack2(t4.x, t4.y));
                ffma2(acc1, a2, pack2(t4.z, t4.w));
            }
        }
        float o0, o1, o2, o3;
        unpack2(acc0, o0, o1);
        unpack2(acc1, o2, o3);
        float h0 = __bfloat162float(__float2bfloat16(o0));
        float h1 = __bfloat162float(__float2bfloat16(o1));
        float h2 = __bfloat162float(__float2bfloat16(o2));
        float h3 = __bfloat162float(__float2bfloat16(o3));
        uint2 hi4, lo4;
        hi4.x = bf2pack(o0, o1);       hi4.y = bf2pack(o2, o3);
        lo4.x = bf2pack(o0 - h0, o1 - h1);
        lo4.y = bf2pack(o2 - h2, o3 - h3);
        long base = ((long)n * 8 + hh) * 384;
        *(uint2*)&g_et3[base + c4]       = hi4;
        *(uint2*)&g_et3[base + 192 + c4] = lo4;
    }
}

// ---------------- layernorm + concat (fc epilogue fused; compact split hcat) --------
__global__ void ln_kernel(const float* __restrict__ lng, const float* __restrict__ lnb,
                          const float* __restrict__ nf,  const float* __restrict__ fcb)
{
    const int n = blockIdx.x, tid = threadIdx.x; // 128 threads
    float xv[3];
    int cnt = 0;
    float s = 0.f, sq = 0.f;
    for (int i = tid; i < 320; i += 128) {
        float v = g_x[(long)n * 320 + i] + fcb[i];
        if (i < 128)       v += nf[(long)n * 128 + i];
        else if (i >= 192) v += g_cosph[i - 192];
        xv[cnt++] = v;
        s += v; sq += v * v;
    }
    __shared__ float rs[4], rq[4];
    for (int o = 16; o; o >>= 1) {
        s  += __shfl_xor_sync(0xffffffffu, s,  o);
        sq += __shfl_xor_sync(0xffffffffu, sq, o);
    }
    int wid = tid >> 5, lane = tid & 31;
    if (lane == 0) { rs[wid] = s; rq[wid] = sq; }
    __syncthreads();
    float ts = rs[0] + rs[1] + rs[2] + rs[3];
    float tq = rq[0] + rq[1] + rq[2] + rq[3];
    float mu = ts * (1.f / 320.f);
    float var = tq * (1.f / 320.f) - mu * mu;
    float inv = rsqrtf(var + 1e-5f);
    long b = (long)n * 896;
    cnt = 0;
    for (int i = tid; i < 320; i += 128) {
        float w = lng[i] * (xv[cnt++] - mu) * inv + lnb[i];
        int c = 128 + i;
        __nv_bfloat16 hi = __float2bfloat16(w);
        __nv_bfloat16 lo = __float2bfloat16(w - __bfloat162float(hi));
        g_hcat3[b + c] = hi;
        g_hcat3[b + 448 + c] = lo;
    }
    {
        float w = nf[(long)n * 128 + tid];
        __nv_bfloat16 hi = __float2bfloat16(w);
        __nv_bfloat16 lo = __float2bfloat16(w - __bfloat162float(hi));
        g_hcat3[b + tid] = hi;
        g_hcat3[b + 448 + tid] = lo;
    }
}

// ---------------- launch ----------------
extern "C" void kernel_launch(void* const* d_in, const int* in_sizes, int n_in,
                              void* d_out, int out_size) {
    const float* nf   = (const float*)d_in[0];
    const float* ef   = (const float*)d_in[1];
    const float* dt   = (const float*)d_in[2];
    const int*   nidx = (const int*)  d_in[3];
    const float* freq = (const float*)d_in[4];
    const float* ph   = (const float*)d_in[5];
    const float* wqs  = (const float*)d_in[6];
    const float* wks  = (const float*)d_in[7];
    const float* wvs  = (const float*)d_in[8];
    const float* fcw  = (const float*)d_in[9];
    const float* fcb  = (const float*)d_in[10];
    const float* lng  = (const float*)d_in[11];
    const float* lnb  = (const float*)d_in[12];
    const float* nw   = (const float*)d_in[13];
    const float* nb   = (const float*)d_in[14];
    float* out = (float*)d_out;

    float *p_proj, *p_wfold, *p_ctx, *p_x, *p_biasq;
    __nv_bfloat16 *p_A3, *p_B3, *p_qh3, *p_wk3, *p_et3, *p_wv3, *p_ctx3, *p_fcw3, *p_hcat3, *p_nodew3;
    cudaGetSymbolAddress((void**)&p_proj,   g_proj);
    cudaGetSymbolAddress((void**)&p_wfold,  g_wfold);
    cudaGetSymbolAddress((void**)&p_ctx,    g_ctx);
    cudaGetSymbolAddress((void**)&p_x,      g_x);
    cudaGetSymbolAddress((void**)&p_biasq,  g_biasq);
    cudaGetSymbolAddress((void**)&p_A3,     g_A3);
    cudaGetSymbolAddress((void**)&p_B3,     g_B3);
    cudaGetSymbolAddress((void**)&p_qh3,    g_qh3);
    cudaGetSymbolAddress((void**)&p_wk3,    g_wk3);
    cudaGetSymbolAddress((void**)&p_et3,    g_et3);
    cudaGetSymbolAddress((void**)&p_wv3,    g_wv3);
    cudaGetSymbolAddress((void**)&p_ctx3,   g_ctx3);
    cudaGetSymbolAddress((void**)&p_fcw3,   g_fcw3);
    cudaGetSymbolAddress((void**)&p_hcat3,  g_hcat3);
    cudaGetSymbolAddress((void**)&p_nodew3, g_nodew3);

    // maximize shared-memory carveout for the wmma kernels (occupancy)
    cudaFuncSetAttribute(wmma_gemm<128,128,4,128>, cudaFuncAttributePreferredSharedMemoryCarveout, 100);
    cudaFuncSetAttribute(wmma_gemm<128,64,0,64>,   cudaFuncAttributePreferredSharedMemoryCarveout, 100);
    cudaFuncSetAttribute(wmma_gemm<128,64,2,192>,  cudaFuncAttributePreferredSharedMemoryCarveout, 100);
    cudaFuncSetAttribute(wmma_gemm<128,64,0,512>,  cudaFuncAttributePreferredSharedMemoryCarveout, 100);
    cudaFuncSetAttribute(wmma_gemm<128,64,3,448>,  cudaFuncAttributePreferredSharedMemoryCarveout, 100);

    // 1) weight splits + biasq + cosph; 2) input split
    prep_kernel<<<(1229440 + 255) / 256, 256>>>(wks, wvs, wqs, fcw, nw, ph);
    convA_kernel<<<(N_SRC * 128 + 255) / 256, 256>>>(nf);

    // 3) node_k|node_v|qh projection (single launch; qh tiles get bias + compact qh3 split)
    wmma_gemm<128,128,4,128><<<dim3(12, 128), 256>>>(p_A3, p_B3, p_proj, 384, 256, 256, 1536,
                                                     0, 0, 0, p_biasq, p_qh3);

    // 4) fold q into K-weights (tensor, batched per head)  [profiled launch]
    wmma_gemm<128,64,0,64><<<dim3(3, 64, 8), 256>>>(p_qh3, p_wk3, p_wfold, 192, 1024, 128, 1536,
                                                    128, (long)192 * 128, 192, nullptr, nullptr);

    // 5) fused attention per dst (writes g_ctx fp32 + compact g_et3)
    attn_kernel<<<N_DST, 256>>>(ef, dt, nidx, freq, ph);

    // 6) V projection (tensor, batched, accumulate onto ctx, emit compact ctx3)
    wmma_gemm<128,64,2,192><<<dim3(1, 64, 8), 256>>>(p_et3, p_wv3, p_ctx, 576, 3072, 384, 512,
                                                     384, (long)64 * 384, 64, nullptr, p_ctx3);

    // 7) fc (tensor); epilogue fused in ln
    wmma_gemm<128,64,0,512><<<dim3(5, 64), 256>>>(p_ctx3, p_fcw3, p_x, 1536, 1024, 1024, 320,
                                                  0, 0, 0, nullptr, nullptr);

    // 8) layernorm + concat (writes compact split hcat)
    ln_kernel<<<N_DST, 128>>>(lng, lnb, nf, fcb);

    // 9) final (tensor), bias+relu fused, writes out directly
    wmma_gemm<128,64,3,448><<<dim3(2, 64), 256>>>(p_hcat3, p_nodew3, out, 1344, 896, 896, 128,
                                                  0, 0, 0, nb, nullptr);
}

// round 14
// speedup vs baseline: 1.0526x; 1.0526x over previous
#include <cuda_runtime.h>
#include <cuda_bf16.h>
#include <mma.h>
#include <math.h>

using namespace nvcuda;

#define N_SRC   16384
#define N_DST   8192

// ---------------- scratch (device globals; no allocations) ----------------
__device__ float g_proj[(long)N_SRC * 1536];   // [0:512) node_k | [512:1024) node_v | [1024:1536) qh
__device__ float g_biasq[512];
__device__ float g_cosph[128];
__device__ float g_wfold[(long)N_DST * 1536];
__device__ float g_ctx[(long)N_DST * 512];
__device__ float g_x[(long)N_DST * 320];
// bf16-split operands (A-style = [hi|lo|hi], B-style = [hi|hi|lo])
__device__ __nv_bfloat16 g_A3[(long)N_SRC * 384];
__device__ __nv_bfloat16 g_B3[(long)1536 * 384];
__device__ __nv_bfloat16 g_qh3[(long)N_DST * 1536];
__device__ __nv_bfloat16 g_wk3[8 * 192 * 192];
__device__ __nv_bfloat16 g_et3[(long)N_DST * 4608];
__device__ __nv_bfloat16 g_wv3[8 * 64 * 576];
__device__ __nv_bfloat16 g_ctx3[(long)N_DST * 1536];
__device__ __nv_bfloat16 g_fcw3[(long)320 * 1536];
__device__ __nv_bfloat16 g_hcat3[(long)N_DST * 1344];
__device__ __nv_bfloat16 g_nodew3[(long)128 * 1344];

// ---------------- helpers ----------------
__device__ __forceinline__ unsigned long long pack2(float x, float y) {
    unsigned long long r;
    asm("mov.b64 %0, {%1, %2};" : "=l"(r) : "f"(x), "f"(y));
    return r;
}
__device__ __forceinline__ void unpack2(unsigned long long v, float& x, float& y) {
    asm("mov.b64 {%0, %1}, %2;" : "=f"(x), "=f"(y) : "l"(v));
}
__device__ __forceinline__ void ffma2(unsigned long long& d, unsigned long long a, unsigned long long b) {
    asm("fma.rn.f32x2 %0, %1, %2, %0;" : "+l"(d) : "l"(a), "l"(b));
}
__device__ __forceinline__ __nv_bfloat16 bsplit(float v, int is_lo) {
    __nv_bfloat16 h = __float2bfloat16(v);
    if (!is_lo) return h;
    return __float2bfloat16(v - __bfloat162float(h));
}
__device__ __forceinline__ unsigned int bf2pack(float a, float b) {
    __nv_bfloat162 t;
    t.x = __float2bfloat16(a);
    t.y = __float2bfloat16(b);
    return *(unsigned int*)&t;
}
__device__ __forceinline__ void cp16(unsigned int saddr, const void* gptr) {
    asm volatile("cp.async.cg.shared.global [%0], [%1], 16;" :: "r"(saddr), "l"(gptr) : "memory");
}
__device__ __forceinline__ void cp_commit() {
    asm volatile("cp.async.commit_group;" ::: "memory");
}
template<int N>
__device__ __forceinline__ void cp_wait() {
    asm volatile("cp.async.wait_group %0;" :: "n"(N) : "memory");
}

// ---------------- prep: all static weight splits + biasq + cosph ----------------
__global__ void prep_kernel(const float* __restrict__ wks, const float* __restrict__ wvs,
                            const float* __restrict__ wqs, const float* __restrict__ fcw,
                            const float* __restrict__ nw,  const float* __restrict__ ph)
{
    const int S0 = 589824;             // B3: 1536 x 384
    const int S1 = S0 + 294912;        // wk3: 8 x 192 x 192
    const int S2 = S1 + 294912;        // wv3: 8 x 64 x 576
    const int S3 = S2 + 491520;        // fcw3: 320 x 1536
    const int S4 = S3 + 172032;        // nodew3: 128 x 1344
    const int S5 = S4 + 512;           // biasq
    const int S6 = S5 + 128;           // cosph
    int t = blockIdx.x * blockDim.x + threadIdx.x;
    if (t < S0) {
        int r = t / 384, kp = t % 384;
        int k = kp & 127, seg = kp >> 7;
        float v;
        if (r < 512)       v = wks[r * 320 + k];
        else if (r < 1024) v = wvs[(r - 512) * 320 + k];
        else               v = wqs[(r - 1024) * 320 + k];
        g_B3[t] = bsplit(v, seg == 2);
    } else if (t < S1) {
        int i = t - S0;
        int h = i / 36864, rem = i % 36864;
        int c = rem / 192, kp = rem % 192;
        int d = kp & 63, seg = kp >> 6;
        float v = wks[(h * 64 + d) * 320 + 128 + c];
        g_wk3[i] = bsplit(v, seg == 2);
    } else if (t < S2) {
        int i = t - S1;
        int h = i / 36864, rem = i % 36864;
        int d = rem / 576, kp = rem % 576;
        int c = kp % 192, seg = kp / 192;
        float v = wvs[(h * 64 + d) * 320 + 128 + c];
        g_wv3[i] = bsplit(v, seg == 2);
    } else if (t < S3) {
        int i = t - S2;
        int c = i / 1536, kp = i % 1536;
        int j = kp & 511, seg = kp >> 9;
        float v = fcw[c * 512 + j];
        g_fcw3[i] = bsplit(v, seg == 2);
    } else if (t < S4) {
        int i = t - S3;
        int o = i / 1344, kp = i % 1344;
        int c = kp % 448, seg = kp / 448;
        float v = nw[o * 448 + c];
        g_nodew3[i] = bsplit(v, seg == 2);
    } else if (t < S5) {
        int j = t - S4;
        float acc = 0.f;
        for (int d = 0; d < 128; d++) acc += cosf(ph[d]) * wqs[j * 320 + 192 + d];
        g_biasq[j] = acc;
    } else if (t < S6) {
        g_cosph[t - S5] = cosf(ph[t - S5]);
    }
}

// ---------------- conversion ----------------
__global__ void convA_kernel(const float* __restrict__ nf) {
    int i = blockIdx.x * 256 + threadIdx.x;
    if (i < N_SRC * 128) {
        int m = i >> 7, k = i & 127;
        float v = nf[i];
        __nv_bfloat16 hi = __float2bfloat16(v);
        __nv_bfloat16 lo = __float2bfloat16(v - __bfloat162float(hi));
        long b = (long)m * 384;
        g_A3[b + k] = hi;
        g_A3[b + 128 + k] = lo;
        g_A3[b + 256 + k] = hi;
    }
}

// ---------------- bf16 wmma GEMM, BK=64, cp.async 2-stage smem pipeline ------------
// EPI: 0 plain store;
//      2 accumulate(init from C) -> also write bf16-split to aux_bf (ctx3 layout);
//      3 relu(v + aux_f[col]) -> store to C;
//      4 plain store + fused qh epilogue (tiles with tn0>=1024 && tm0<N_DST);
//        blocks with tn0>=1024 && tm0>=N_DST produce unused data -> early exit.
template<int BM, int BN, int EPI>
__global__ void __launch_bounds__(256, 3)
wmma_gemm(const __nv_bfloat16* __restrict__ A,
          const __nv_bfloat16* __restrict__ Bt,
          float* __restrict__ C,
          int K3, int lda, int ldb, int ldc,
          long bsA, long bsB, long bsC,
          const float* __restrict__ aux_f,
          __nv_bfloat16* __restrict__ aux_bf)
{
    constexpr int BK = 64;
    constexpr int PAD = 8;
    constexpr int LDSH = BK + PAD;
    constexpr int CPR = BK / 8;                 // 16B chunks per row
    constexpr int FR_M = BM / 64;
    constexpr int FR_N = BN / 32;
    constexpr int A_LD = BM * CPR / 256;
    constexpr int B_LD = BN * CPR / 256;
    __shared__ __align__(16) __nv_bfloat16 sbuf[2][(BM + BN) * LDSH];
    const int bz = blockIdx.z;
    A += (long)bz * bsA; Bt += (long)bz * bsB; C += (long)bz * bsC;
    const int tid = threadIdx.x;
    const int wid = tid >> 5;
    const int wm = wid & 3;
    const int wn = wid >> 2;
    const int tm0 = blockIdx.y * BM;
    const int tn0 = blockIdx.x * BN;

    // qh columns are only consumed for rows < N_DST — skip the dead blocks entirely
    if (EPI == 4 && tn0 >= 1024 && tm0 >= N_DST) return;

    wmma::fragment<wmma::accumulator, 16, 16, 16, float> cf[FR_M][FR_N];
#pragma unroll
    for (int i = 0; i < FR_M; i++)
#pragma unroll
        for (int j = 0; j < FR_N; j++) {
            if (EPI == 2)
                wmma::load_matrix_sync(cf[i][j],
                    &C[(long)(tm0 + wm * 32 + i * 16) * ldc + tn0 + wn * (BN / 2) + j * 16],
                    ldc, wmma::mem_row_major);
            else
                wmma::fill_fragment(cf[i][j], 0.f);
        }

    auto loadStage = [&](int st, int k0) {
#pragma unroll
        for (int it = 0; it < A_LD; it++) {
            int idx = tid + it * 256;
            int r = idx / CPR, c8 = idx % CPR;
            cp16((unsigned int)__cvta_generic_to_shared(&sbuf[st][r * LDSH + c8 * 8]),
                 &A[(long)(tm0 + r) * lda + k0 + c8 * 8]);
        }
#pragma unroll
        for (int it = 0; it < B_LD; it++) {
            int idx = tid + it * 256;
            int r = idx / CPR, c8 = idx % CPR;
            cp16((unsigned int)__cvta_generic_to_shared(&sbuf[st][(BM + r) * LDSH + c8 * 8]),
                 &Bt[(long)(tn0 + r) * ldb + k0 + c8 * 8]);
        }
        cp_commit();
    };

    const int nIter = K3 / BK;
    loadStage(0, 0);
    for (int it = 0; it < nIter; it++) {
        int st = it & 1;
        if (it + 1 < nIter) {
            loadStage(st ^ 1, (it + 1) * BK);
            cp_wait<1>();
        } else {
            cp_wait<0>();
        }
        __syncthreads();
#pragma unroll
        for (int kk = 0; kk < BK; kk += 16) {
            wmma::fragment<wmma::matrix_a, 16, 16, 16, __nv_bfloat16, wmma::row_major> af[FR_M];
            wmma::fragment<wmma::matrix_b, 16, 16, 16, __nv_bfloat16, wmma::col_major> bf[FR_N];
#pragma unroll
            for (int i = 0; i < FR_M; i++)
                wmma::load_matrix_sync(af[i], &sbuf[st][(wm * 32 + i * 16) * LDSH + kk], LDSH);
#pragma unroll
            for (int j = 0; j < FR_N; j++)
                wmma::load_matrix_sync(bf[j], &sbuf[st][(BM + wn * (BN / 2) + j * 16) * LDSH + kk], LDSH);
#pragma unroll
            for (int i = 0; i < FR_M; i++)
#pragma unroll
                for (int j = 0; j < FR_N; j++)
                    wmma::mma_sync(cf[i][j], af[i], bf[j], cf[i][j]);
        }
        __syncthreads();
    }

    if (EPI == 0 || EPI == 4) {
#pragma unroll
        for (int i = 0; i < FR_M; i++)
#pragma unroll
            for (int j = 0; j < FR_N; j++)
                wmma::store_matrix_sync(&C[(long)(tm0 + wm * 32 + i * 16) * ldc + tn0 + wn * (BN / 2) + j * 16],
                                        cf[i][j], ldc, wmma::mem_row_major);
        if (EPI == 4) {
            __syncthreads();
            if (tn0 >= 1024 && tm0 < N_DST) {
                for (int idx = tid; idx < BM * BN; idx += 256) {
                    int r = idx / BN, c = idx % BN;
                    int row = tm0 + r;
                    if (row < N_DST) {
                        int col = tn0 + c;
                        long off = (long)row * ldc + col;
                        int j = col - 1024;
                        float v = C[off] + aux_f[j];
                        C[off] = v;
                        int h = j >> 6, d = j & 63;
                        __nv_bfloat16 hi = __float2bfloat16(v);
                        __nv_bfloat16 lo = __float2bfloat16(v - __bfloat162float(hi));
                        long b = (long)row * 1536 + h * 192;
                        aux_bf[b + d] = hi;
                        aux_bf[b + 64 + d] = lo;
                        aux_bf[b + 128 + d] = hi;
                    }
                }
            }
        }
    } else {
        float* sC = (float*)&sbuf[0][0];
        static_assert(sizeof(sbuf) >= BM * BN * sizeof(float) || EPI == 0 || EPI == 4, "sC alias too small");
#pragma unroll
        for (int i = 0; i < FR_M; i++)
#pragma unroll
            for (int j = 0; j < FR_N; j++)
                wmma::store_matrix_sync(&sC[(wm * 32 + i * 16) * BN + wn * (BN / 2) + j * 16],
                                        cf[i][j], BN, wmma::mem_row_major);
        __syncthreads();
        for (int idx = tid; idx < BM * BN; idx += 256) {
            int r = idx / BN, c = idx % BN;
            float v = sC[idx];
            int row = tm0 + r;
            if (EPI == 2) {
                int j = bz * 64 + tn0 + c;
                __nv_bfloat16 hi = __float2bfloat16(v);
                __nv_bfloat16 lo = __float2bfloat16(v - __bfloat162float(hi));
                long b = (long)row * 1536 + j;
                aux_bf[b] = hi;
                aux_bf[b + 512] = lo;
                aux_bf[b + 1024] = hi;
            }
            if (EPI == 3) {
                int col = tn0 + c;
                C[(long)row * ldc + col] = fmaxf(v + aux_f[col], 0.f);
            }
        }
    }
}

// ---------------- fused attention kernel: one block per dst node ----------------
__global__ void attn_kernel(const float* __restrict__ ef, const float* __restrict__ dt,
                            const int* __restrict__ nidx,
                            const float* __restrict__ freq, const float* __restrict__ ph)
{
    const int n = blockIdx.x;
    const int tid = threadIdx.x;
    __shared__ __align__(16) float s_qh[512];
    __shared__ __align__(16) float s_wf[1536];
    __shared__ __align__(16) float s_te[32][132];
    __shared__ __align__(16) float s_e[32][68];
    __shared__ float s_dt[32];
    __shared__ int   s_idx[16];
    __shared__ float s_fr[128], s_ph[128];
    __shared__ float s_at[8][33];
    __shared__ float s_a2[8][17];
    __shared__ float s_ns[8][17];

    for (int i = tid; i < 512;  i += 256) s_qh[i] = g_proj[(long)n * 1536 + 1024 + i];
    for (int i = tid; i < 1536; i += 256) s_wf[i] = g_wfold[(long)n * 1536 + i];
    {
        const float4* ef4 = (const float4*)(ef + (long)n * 2048);
        for (int i = tid; i < 512; i += 256) {
            int l = i >> 4, c4 = i & 15;
            *(float4*)&s_e[l][c4 * 4] = ef4[i];
        }
    }
    if (tid < 128) { s_fr[tid] = freq[tid]; s_ph[tid] = ph[tid]; }
    if (tid < 32)  s_dt[tid] = dt[(long)n * 32 + tid];
    if (tid < 16)  s_idx[tid] = nidx[n * 16 + tid];
    __syncthreads();

    // temporal encoding via hardware cos (MUFU pipe)
    for (int i = tid; i < 4096; i += 256) {
        int l = i >> 7, d = i & 127;
        s_te[l][d] = __cosf(fmaf(s_dt[l], s_fr[d], s_ph[d]));
    }
    __syncthreads();

    const int h = tid >> 5, l = tid & 31;

    // node scores (16 distinct neighbors, coalesced)
    {
#pragma unroll
        for (int jb = 0; jb < 16; jb += 4) {
            int j = jb + (l >> 3);
            int d0 = (l & 7) * 8;
            const float4* p = (const float4*)(g_proj + (long)s_idx[j] * 1536 + h * 64 + d0);
            const float4* q = (const float4*)(s_qh + h * 64 + d0);
            float4 x0 = p[0], x1 = p[1];
            float4 q0 = q[0], q1 = q[1];
            float d = x0.x * q0.x + x0.y * q0.y + x0.z * q0.z + x0.w * q0.w
                    + x1.x * q1.x + x1.y * q1.y + x1.z * q1.z + x1.w * q1.w;
            d += __shfl_xor_sync(0xffffffffu, d, 1);
            d += __shfl_xor_sync(0xffffffffu, d, 2);
            d += __shfl_xor_sync(0xffffffffu, d, 4);
            if ((l & 7) == 0) s_ns[h][j] = d;
        }
        __syncwarp();
    }

    // scores + softmax
    {
        float sc = s_ns[h][l >> 1];
        const float4* ev = (const float4*)(&s_e[l][0]);
        const float4* we = (const float4*)(s_wf + h * 192);
#pragma unroll
        for (int j = 0; j < 16; j++) {
            float4 a = ev[j], b = we[j];
            sc += a.x * b.x + a.y * b.y + a.z * b.z + a.w * b.w;
        }
        const float4* tv = (const float4*)(&s_te[l][0]);
        const float4* wt = (const float4*)(s_wf + h * 192 + 64);
#pragma unroll
        for (int j = 0; j < 32; j++) {
            float4 a = tv[j], b = wt[j];
            sc += a.x * b.x + a.y * b.y + a.z * b.z + a.w * b.w;
        }
        sc *= 0.125f;
        float mx = sc;
        for (int o = 16; o; o >>= 1) mx = fmaxf(mx, __shfl_xor_sync(0xffffffffu, mx, o));
        float ex = expf(sc - mx);
        float sm = ex;
        for (int o = 16; o; o >>= 1) sm += __shfl_xor_sync(0xffffffffu, sm, o);
        float p = ex / sm;
        s_at[h][l] = p;
        float pp = p + __shfl_xor_sync(0xffffffffu, p, 1);
        if ((l & 1) == 0) s_a2[h][l >> 1] = pp;
    }
    __syncthreads();

    // ctx node part (fp32, consumed as accumulator-init by wmma5)
    {
        int j = tid * 2;
        int hh = j >> 6;
        unsigned long long acc = 0ull;
#pragma unroll 4
        for (int r = 0; r < 16; r++) {
            float2 v = *(const float2*)&g_proj[(long)s_idx[r] * 1536 + 512 + j];
            float a = s_a2[hh][r];
            ffma2(acc, pack2(a, a), pack2(v.x, v.y));
        }
        float o0, o1;
        unpack2(acc, o0, o1);
        *(float2*)&g_ctx[(long)n * 512 + j] = make_float2(o0, o1);
    }
    // ebar / tbar, float4 (4 columns per work item) -> bf16 [hi|lo|hi] per head
    for (int p = tid; p < 384; p += 256) {
        int hh = p / 48, c4 = (p % 48) * 4;
        unsigned long long acc0 = 0ull, acc1 = 0ull;
        if (c4 < 64) {
#pragma unroll
            for (int ll = 0; ll < 32; ll++) {
                float4 e = *(const float4*)&s_e[ll][c4];
                float a = s_at[hh][ll];
                unsigned long long a2 = pack2(a, a);
                ffma2(acc0, a2, pack2(e.x, e.y));
                ffma2(acc1, a2, pack2(e.z, e.w));
            }
        } else {
            int d = c4 - 64;
#pragma unroll
            for (int ll = 0; ll < 32; ll++) {
                float4 t4 = *(const float4*)&s_te[ll][d];
                float a = s_at[hh][ll];
                unsigned long long a2 = pack2(a, a);
                ffma2(acc0, a2, pack2(t4.x, t4.y));
                ffma2(acc1, a2, pack2(t4.z, t4.w));
            }
        }
        float o0, o1, o2, o3;
        unpack2(acc0, o0, o1);
        unpack2(acc1, o2, o3);
        float h0 = __bfloat162float(__float2bfloat16(o0));
        float h1 = __bfloat162float(__float2bfloat16(o1));
        float h2 = __bfloat162float(__float2bfloat16(o2));
        float h3 = __bfloat162float(__float2bfloat16(o3));
        uint2 hi4, lo4;
        hi4.x = bf2pack(o0, o1);       hi4.y = bf2pack(o2, o3);
        lo4.x = bf2pack(o0 - h0, o1 - h1);
        lo4.y = bf2pack(o2 - h2, o3 - h3);
        long base = ((long)n * 8 + hh) * 576;
        *(uint2*)&g_et3[base + c4]       = hi4;
        *(uint2*)&g_et3[base + 192 + c4] = lo4;
        *(uint2*)&g_et3[base + 384 + c4] = hi4;
    }
}

// ---------------- layernorm + concat (fc epilogue fused; writes split hcat) ----------
__global__ void ln_kernel(const float* __restrict__ lng, const float* __restrict__ lnb,
                          const float* __restrict__ nf,  const float* __restrict__ fcb)
{
    const int n = blockIdx.x, tid = threadIdx.x; // 128 threads
    float xv[3];
    int cnt = 0;
    float s = 0.f, sq = 0.f;
    for (int i = tid; i < 320; i += 128) {
        float v = g_x[(long)n * 320 + i] + fcb[i];
        if (i < 128)       v += nf[(long)n * 128 + i];
        else if (i >= 192) v += g_cosph[i - 192];
        xv[cnt++] = v;
        s += v; sq += v * v;
    }
    __shared__ float rs[4], rq[4];
    for (int o = 16; o; o >>= 1) {
        s  += __shfl_xor_sync(0xffffffffu, s,  o);
        sq += __shfl_xor_sync(0xffffffffu, sq, o);
    }
    int wid = tid >> 5, lane = tid & 31;
    if (lane == 0) { rs[wid] = s; rq[wid] = sq; }
    __syncthreads();
    float ts = rs[0] + rs[1] + rs[2] + rs[3];
    float tq = rq[0] + rq[1] + rq[2] + rq[3];
    float mu = ts * (1.f / 320.f);
    float var = tq * (1.f / 320.f) - mu * mu;
    float inv = rsqrtf(var + 1e-5f);
    long b = (long)n * 1344;
    cnt = 0;
    for (int i = tid; i < 320; i += 128) {
        float w = lng[i] * (xv[cnt++] - mu) * inv + lnb[i];
        int c = 128 + i;
        __nv_bfloat16 hi = __float2bfloat16(w);
        __nv_bfloat16 lo = __float2bfloat16(w - __bfloat162float(hi));
        g_hcat3[b + c] = hi;
        g_hcat3[b + 448 + c] = lo;
        g_hcat3[b + 896 + c] = hi;
    }
    {
        float w = nf[(long)n * 128 + tid];
        __nv_bfloat16 hi = __float2bfloat16(w);
        __nv_bfloat16 lo = __float2bfloat16(w - __bfloat162float(hi));
        g_hcat3[b + tid] = hi;
        g_hcat3[b + 448 + tid] = lo;
        g_hcat3[b + 896 + tid] = hi;
    }
}

// ---------------- launch ----------------
extern "C" void kernel_launch(void* const* d_in, const int* in_sizes, int n_in,
                              void* d_out, int out_size) {
    const float* nf   = (const float*)d_in[0];
    const float* ef   = (const float*)d_in[1];
    const float* dt   = (const float*)d_in[2];
    const int*   nidx = (const int*)  d_in[3];
    const float* freq = (const float*)d_in[4];
    const float* ph   = (const float*)d_in[5];
    const float* wqs  = (const float*)d_in[6];
    const float* wks  = (const float*)d_in[7];
    const float* wvs  = (const float*)d_in[8];
    const float* fcw  = (const float*)d_in[9];
    const float* fcb  = (const float*)d_in[10];
    const float* lng  = (const float*)d_in[11];
    const float* lnb  = (const float*)d_in[12];
    const float* nw   = (const float*)d_in[13];
    const float* nb   = (const float*)d_in[14];
    float* out = (float*)d_out;

    float *p_proj, *p_wfold, *p_ctx, *p_x, *p_biasq;
    __nv_bfloat16 *p_A3, *p_B3, *p_qh3, *p_wk3, *p_et3, *p_wv3, *p_ctx3, *p_fcw3, *p_hcat3, *p_nodew3;
    cudaGetSymbolAddress((void**)&p_proj,   g_proj);
    cudaGetSymbolAddress((void**)&p_wfold,  g_wfold);
    cudaGetSymbolAddress((void**)&p_ctx,    g_ctx);
    cudaGetSymbolAddress((void**)&p_x,      g_x);
    cudaGetSymbolAddress((void**)&p_biasq,  g_biasq);
    cudaGetSymbolAddress((void**)&p_A3,     g_A3);
    cudaGetSymbolAddress((void**)&p_B3,     g_B3);
    cudaGetSymbolAddress((void**)&p_qh3,    g_qh3);
    cudaGetSymbolAddress((void**)&p_wk3,    g_wk3);
    cudaGetSymbolAddress((void**)&p_et3,    g_et3);
    cudaGetSymbolAddress((void**)&p_wv3,    g_wv3);
    cudaGetSymbolAddress((void**)&p_ctx3,   g_ctx3);
    cudaGetSymbolAddress((void**)&p_fcw3,   g_fcw3);
    cudaGetSymbolAddress((void**)&p_hcat3,  g_hcat3);
    cudaGetSymbolAddress((void**)&p_nodew3, g_nodew3);

    // maximize shared-memory carveout for the wmma kernels (occupancy)
    cudaFuncSetAttribute(wmma_gemm<128,128,4>, cudaFuncAttributePreferredSharedMemoryCarveout, 100);
    cudaFuncSetAttribute(wmma_gemm<128,64,0>,  cudaFuncAttributePreferredSharedMemoryCarveout, 100);
    cudaFuncSetAttribute(wmma_gemm<128,64,2>,  cudaFuncAttributePreferredSharedMemoryCarveout, 100);
    cudaFuncSetAttribute(wmma_gemm<128,64,3>,  cudaFuncAttributePreferredSharedMemoryCarveout, 100);

    // 1) weight splits + biasq + cosph; 2) input split
    prep_kernel<<<(1843840 + 255) / 256, 256>>>(wks, wvs, wqs, fcw, nw, ph);
    convA_kernel<<<(N_SRC * 128 + 255) / 256, 256>>>(nf);

    // 3) node_k|node_v|qh projection (tensor), qh-bias + qh3 split fused in epilogue;
    //    dead qh blocks (rows >= N_DST) early-exit
    wmma_gemm<128,128,4><<<dim3(12, 128), 256>>>(p_A3, p_B3, p_proj, 384, 384, 384, 1536,
                                                 0, 0, 0, p_biasq, p_qh3);

    // 4) fold q into K-weights (tensor, batched per head)  [profiled launch]
    wmma_gemm<128,64,0><<<dim3(3, 64, 8), 256>>>(p_qh3, p_wk3, p_wfold, 192, 1536, 192, 1536,
                                                 192, (long)192 * 192, 192, nullptr, nullptr);

    // 5) fused attention per dst (writes g_ctx fp32 + g_et3 split)
    attn_kernel<<<N_DST, 256>>>(ef, dt, nidx, freq, ph);

    // 6) V projection (tensor, batched, accumulate onto ctx, emit ctx3 split)
    wmma_gemm<128,64,2><<<dim3(1, 64, 8), 256>>>(p_et3, p_wv3, p_ctx, 576, 4608, 576, 512,
                                                 576, (long)64 * 576, 64, nullptr, p_ctx3);

    // 7) fc (tensor); epilogue fused in ln
    wmma_gemm<128,64,0><<<dim3(5, 64), 256>>>(p_ctx3, p_fcw3, p_x, 1536, 1536, 1536, 320,
                                              0, 0, 0, nullptr, nullptr);

    // 8) layernorm + concat (writes split hcat)
    ln_kernel<<<N_DST, 128>>>(lng, lnb, nf, fcb);

    // 9) final (tensor), bias+relu fused, writes out directly
    wmma_gemm<128,64,3><<<dim3(2, 64), 256>>>(p_hcat3, p_nodew3, out, 1344, 1344, 1344, 128,
                                              0, 0, 0, nb, nullptr);
}

// round 15
// speedup vs baseline: 1.1328x; 1.0761x over previous
#include <cuda_runtime.h>
#include <cuda_bf16.h>
#include <mma.h>
#include <math.h>

using namespace nvcuda;

#define N_SRC   16384
#define N_DST   8192

// ---------------- scratch (device globals; no allocations) ----------------
__device__ float g_proj[(long)N_SRC * 1536];   // [0:512) node_k | [512:1024) node_v | [1024:1536) qh
__device__ float g_biasq[512];
__device__ float g_cosph[128];
__device__ float g_wfold[(long)N_DST * 1536];
__device__ float g_ctx[(long)N_DST * 512];
__device__ float g_x[(long)N_DST * 320];
// bf16-split operands (A-style = [hi|lo|hi], B-style = [hi|hi|lo])
__device__ __nv_bfloat16 g_A3[(long)N_SRC * 384];
__device__ __nv_bfloat16 g_B3[(long)1536 * 384];
__device__ __nv_bfloat16 g_qh3[(long)N_DST * 1536];
__device__ __nv_bfloat16 g_wk3[8 * 192 * 192];
__device__ __nv_bfloat16 g_et3[(long)N_DST * 4608];
__device__ __nv_bfloat16 g_wv3[8 * 64 * 576];
__device__ __nv_bfloat16 g_ctx3[(long)N_DST * 1536];
__device__ __nv_bfloat16 g_fcw3[(long)320 * 1536];
__device__ __nv_bfloat16 g_hcat3[(long)N_DST * 1344];
__device__ __nv_bfloat16 g_nodew3[(long)128 * 1344];

// ---------------- helpers ----------------
__device__ __forceinline__ unsigned long long pack2(float x, float y) {
    unsigned long long r;
    asm("mov.b64 %0, {%1, %2};" : "=l"(r) : "f"(x), "f"(y));
    return r;
}
__device__ __forceinline__ void unpack2(unsigned long long v, float& x, float& y) {
    asm("mov.b64 {%0, %1}, %2;" : "=f"(x), "=f"(y) : "l"(v));
}
__device__ __forceinline__ void ffma2(unsigned long long& d, unsigned long long a, unsigned long long b) {
    asm("fma.rn.f32x2 %0, %1, %2, %0;" : "+l"(d) : "l"(a), "l"(b));
}
__device__ __forceinline__ __nv_bfloat16 bsplit(float v, int is_lo) {
    __nv_bfloat16 h = __float2bfloat16(v);
    if (!is_lo) return h;
    return __float2bfloat16(v - __bfloat162float(h));
}
__device__ __forceinline__ unsigned int bf2pack(float a, float b) {
    __nv_bfloat162 t;
    t.x = __float2bfloat16(a);
    t.y = __float2bfloat16(b);
    return *(unsigned int*)&t;
}
__device__ __forceinline__ void cp16(unsigned int saddr, const void* gptr) {
    asm volatile("cp.async.cg.shared.global [%0], [%1], 16;" :: "r"(saddr), "l"(gptr) : "memory");
}
__device__ __forceinline__ void cp_commit() {
    asm volatile("cp.async.commit_group;" ::: "memory");
}
template<int N>
__device__ __forceinline__ void cp_wait() {
    asm volatile("cp.async.wait_group %0;" :: "n"(N) : "memory");
}

// ---------------- prep: all static weight splits + biasq + cosph ----------------
__global__ void prep_kernel(const float* __restrict__ wks, const float* __restrict__ wvs,
                            const float* __restrict__ wqs, const float* __restrict__ fcw,
                            const float* __restrict__ nw,  const float* __restrict__ ph)
{
    const int S0 = 589824;             // B3: 1536 x 384
    const int S1 = S0 + 294912;        // wk3: 8 x 192 x 192
    const int S2 = S1 + 294912;        // wv3: 8 x 64 x 576
    const int S3 = S2 + 491520;        // fcw3: 320 x 1536
    const int S4 = S3 + 172032;        // nodew3: 128 x 1344
    const int S5 = S4 + 512;           // biasq
    const int S6 = S5 + 128;           // cosph
    int t = blockIdx.x * blockDim.x + threadIdx.x;
    if (t < S0) {
        int r = t / 384, kp = t % 384;
        int k = kp & 127, seg = kp >> 7;
        float v;
        if (r < 512)       v = wks[r * 320 + k];
        else if (r < 1024) v = wvs[(r - 512) * 320 + k];
        else               v = wqs[(r - 1024) * 320 + k];
        g_B3[t] = bsplit(v, seg == 2);
    } else if (t < S1) {
        int i = t - S0;
        int h = i / 36864, rem = i % 36864;
        int c = rem / 192, kp = rem % 192;
        int d = kp & 63, seg = kp >> 6;
        float v = wks[(h * 64 + d) * 320 + 128 + c];
        g_wk3[i] = bsplit(v, seg == 2);
    } else if (t < S2) {
        int i = t - S1;
        int h = i / 36864, rem = i % 36864;
        int d = rem / 576, kp = rem % 576;
        int c = kp % 192, seg = kp / 192;
        float v = wvs[(h * 64 + d) * 320 + 128 + c];
        g_wv3[i] = bsplit(v, seg == 2);
    } else if (t < S3) {
        int i = t - S2;
        int c = i / 1536, kp = i % 1536;
        int j = kp & 511, seg = kp >> 9;
        float v = fcw[c * 512 + j];
        g_fcw3[i] = bsplit(v, seg == 2);
    } else if (t < S4) {
        int i = t - S3;
        int o = i / 1344, kp = i % 1344;
        int c = kp % 448, seg = kp / 448;
        float v = nw[o * 448 + c];
        g_nodew3[i] = bsplit(v, seg == 2);
    } else if (t < S5) {
        int j = t - S4;
        float acc = 0.f;
        for (int d = 0; d < 128; d++) acc += cosf(ph[d]) * wqs[j * 320 + 192 + d];
        g_biasq[j] = acc;
    } else if (t < S6) {
        g_cosph[t - S5] = cosf(ph[t - S5]);
    }
}

// ---------------- conversion ----------------
__global__ void convA_kernel(const float* __restrict__ nf) {
    int i = blockIdx.x * 256 + threadIdx.x;
    if (i < N_SRC * 128) {
        int m = i >> 7, k = i & 127;
        float v = nf[i];
        __nv_bfloat16 hi = __float2bfloat16(v);
        __nv_bfloat16 lo = __float2bfloat16(v - __bfloat162float(hi));
        long b = (long)m * 384;
        g_A3[b + k] = hi;
        g_A3[b + 128 + k] = lo;
        g_A3[b + 256 + k] = hi;
    }
}

// ---------------- bf16 wmma GEMM, BK=64, cp.async 2-stage smem pipeline ------------
// EPI: 0 plain store;
//      2 accumulate(init from C) -> also write bf16-split to aux_bf (ctx3 layout);
//      3 relu(v + aux_f[col]) -> store to C;
//      4 plain store + fused qh epilogue (tiles with tn0>=1024 && tm0<N_DST);
//        blocks with tn0>=1024 && tm0>=N_DST produce unused data -> early exit.
template<int BM, int BN, int EPI>
__global__ void wmma_gemm(const __nv_bfloat16* __restrict__ A,
                          const __nv_bfloat16* __restrict__ Bt,
                          float* __restrict__ C,
                          int K3, int lda, int ldb, int ldc,
                          long bsA, long bsB, long bsC,
                          const float* __restrict__ aux_f,
                          __nv_bfloat16* __restrict__ aux_bf)
{
    constexpr int BK = 64;
    constexpr int PAD = 8;
    constexpr int LDSH = BK + PAD;
    constexpr int CPR = BK / 8;                 // 16B chunks per row
    constexpr int FR_M = BM / 64;
    constexpr int FR_N = BN / 32;
    constexpr int A_LD = BM * CPR / 256;
    constexpr int B_LD = BN * CPR / 256;
    __shared__ __align__(16) __nv_bfloat16 sbuf[2][(BM + BN) * LDSH];
    const int bz = blockIdx.z;
    A += (long)bz * bsA; Bt += (long)bz * bsB; C += (long)bz * bsC;
    const int tid = threadIdx.x;
    const int wid = tid >> 5;
    const int wm = wid & 3;
    const int wn = wid >> 2;
    const int tm0 = blockIdx.y * BM;
    const int tn0 = blockIdx.x * BN;

    // qh columns are only consumed for rows < N_DST — skip dead blocks entirely
    if (EPI == 4 && tn0 >= 1024 && tm0 >= N_DST) return;

    wmma::fragment<wmma::accumulator, 16, 16, 16, float> cf[FR_M][FR_N];
#pragma unroll
    for (int i = 0; i < FR_M; i++)
#pragma unroll
        for (int j = 0; j < FR_N; j++) {
            if (EPI == 2)
                wmma::load_matrix_sync(cf[i][j],
                    &C[(long)(tm0 + wm * 32 + i * 16) * ldc + tn0 + wn * (BN / 2) + j * 16],
                    ldc, wmma::mem_row_major);
            else
                wmma::fill_fragment(cf[i][j], 0.f);
        }

    auto loadStage = [&](int st, int k0) {
#pragma unroll
        for (int it = 0; it < A_LD; it++) {
            int idx = tid + it * 256;
            int r = idx / CPR, c8 = idx % CPR;
            cp16((unsigned int)__cvta_generic_to_shared(&sbuf[st][r * LDSH + c8 * 8]),
                 &A[(long)(tm0 + r) * lda + k0 + c8 * 8]);
        }
#pragma unroll
        for (int it = 0; it < B_LD; it++) {
            int idx = tid + it * 256;
            int r = idx / CPR, c8 = idx % CPR;
            cp16((unsigned int)__cvta_generic_to_shared(&sbuf[st][(BM + r) * LDSH + c8 * 8]),
                 &Bt[(long)(tn0 + r) * ldb + k0 + c8 * 8]);
        }
        cp_commit();
    };

    const int nIter = K3 / BK;
    loadStage(0, 0);
    for (int it = 0; it < nIter; it++) {
        int st = it & 1;
        if (it + 1 < nIter) {
            loadStage(st ^ 1, (it + 1) * BK);
            cp_wait<1>();
        } else {
            cp_wait<0>();
        }
        __syncthreads();
#pragma unroll
        for (int kk = 0; kk < BK; kk += 16) {
            wmma::fragment<wmma::matrix_a, 16, 16, 16, __nv_bfloat16, wmma::row_major> af[FR_M];
            wmma::fragment<wmma::matrix_b, 16, 16, 16, __nv_bfloat16, wmma::col_major> bf[FR_N];
#pragma unroll
            for (int i = 0; i < FR_M; i++)
                wmma::load_matrix_sync(af[i], &sbuf[st][(wm * 32 + i * 16) * LDSH + kk], LDSH);
#pragma unroll
            for (int j = 0; j < FR_N; j++)
                wmma::load_matrix_sync(bf[j], &sbuf[st][(BM + wn * (BN / 2) + j * 16) * LDSH + kk], LDSH);
#pragma unroll
            for (int i = 0; i < FR_M; i++)
#pragma unroll
                for (int j = 0; j < FR_N; j++)
                    wmma::mma_sync(cf[i][j], af[i], bf[j], cf[i][j]);
        }
        __syncthreads();
    }

    if (EPI == 0 || EPI == 4) {
#pragma unroll
        for (int i = 0; i < FR_M; i++)
#pragma unroll
            for (int j = 0; j < FR_N; j++)
                wmma::store_matrix_sync(&C[(long)(tm0 + wm * 32 + i * 16) * ldc + tn0 + wn * (BN / 2) + j * 16],
                                        cf[i][j], ldc, wmma::mem_row_major);
        if (EPI == 4) {
            __syncthreads();
            if (tn0 >= 1024 && tm0 < N_DST) {
                for (int idx = tid; idx < BM * BN; idx += 256) {
                    int r = idx / BN, c = idx % BN;
                    int row = tm0 + r;
                    if (row < N_DST) {
                        int col = tn0 + c;
                        long off = (long)row * ldc + col;
                        int j = col - 1024;
                        float v = C[off] + aux_f[j];
                        C[off] = v;
                        int h = j >> 6, d = j & 63;
                        __nv_bfloat16 hi = __float2bfloat16(v);
                        __nv_bfloat16 lo = __float2bfloat16(v - __bfloat162float(hi));
                        long b = (long)row * 1536 + h * 192;
                        aux_bf[b + d] = hi;
                        aux_bf[b + 64 + d] = lo;
                        aux_bf[b + 128 + d] = hi;
                    }
                }
            }
        }
    } else {
        // stage fp32 tile in shared (aliasing the dead pipeline buffers)
        float* sC = (float*)&sbuf[0][0];
        static_assert(sizeof(sbuf) >= BM * BN * sizeof(float) || EPI == 0 || EPI == 4, "sC alias too small");
#pragma unroll
        for (int i = 0; i < FR_M; i++)
#pragma unroll
            for (int j = 0; j < FR_N; j++)
                wmma::store_matrix_sync(&sC[(wm * 32 + i * 16) * BN + wn * (BN / 2) + j * 16],
                                        cf[i][j], BN, wmma::mem_row_major);
        __syncthreads();
        for (int idx = tid; idx < BM * BN; idx += 256) {
            int r = idx / BN, c = idx % BN;
            float v = sC[idx];
            int row = tm0 + r;
            if (EPI == 2) {
                int j = bz * 64 + tn0 + c;
                __nv_bfloat16 hi = __float2bfloat16(v);
                __nv_bfloat16 lo = __float2bfloat16(v - __bfloat162float(hi));
                long b = (long)row * 1536 + j;
                aux_bf[b] = hi;
                aux_bf[b + 512] = lo;
                aux_bf[b + 1024] = hi;
            }
            if (EPI == 3) {
                int col = tn0 + c;
                C[(long)row * ldc + col] = fmaxf(v + aux_f[col], 0.f);
            }
        }
    }
}

// ---------------- fused attention kernel: one block per dst node ----------------
__global__ void attn_kernel(const float* __restrict__ ef, const float* __restrict__ dt,
                            const int* __restrict__ nidx,
                            const float* __restrict__ freq, const float* __restrict__ ph)
{
    const int n = blockIdx.x;
    const int tid = threadIdx.x;
    __shared__ __align__(16) float s_qh[512];
    __shared__ __align__(16) float s_wf[1536];
    __shared__ __align__(16) float s_te[32][132];
    __shared__ __align__(16) float s_e[32][68];
    __shared__ float s_dt[32];
    __shared__ int   s_idx[16];
    __shared__ float s_fr[128], s_ph[128];
    __shared__ float s_at[8][33];
    __shared__ float s_a2[8][17];
    __shared__ float s_ns[8][17];

    for (int i = tid; i < 512;  i += 256) s_qh[i] = g_proj[(long)n * 1536 + 1024 + i];
    for (int i = tid; i < 1536; i += 256) s_wf[i] = g_wfold[(long)n * 1536 + i];
    {
        const float4* ef4 = (const float4*)(ef + (long)n * 2048);
        for (int i = tid; i < 512; i += 256) {
            int l = i >> 4, c4 = i & 15;
            *(float4*)&s_e[l][c4 * 4] = ef4[i];
        }
    }
    if (tid < 128) { s_fr[tid] = freq[tid]; s_ph[tid] = ph[tid]; }
    if (tid < 32)  s_dt[tid] = dt[(long)n * 32 + tid];
    if (tid < 16)  s_idx[tid] = nidx[n * 16 + tid];
    __syncthreads();

    // temporal encoding via hardware cos (MUFU pipe)
    for (int i = tid; i < 4096; i += 256) {
        int l = i >> 7, d = i & 127;
        s_te[l][d] = __cosf(fmaf(s_dt[l], s_fr[d], s_ph[d]));
    }
    __syncthreads();

    const int h = tid >> 5, l = tid & 31;

    // node scores (16 distinct neighbors, coalesced)
    {
#pragma unroll
        for (int jb = 0; jb < 16; jb += 4) {
            int j = jb + (l >> 3);
            int d0 = (l & 7) * 8;
            const float4* p = (const float4*)(g_proj + (long)s_idx[j] * 1536 + h * 64 + d0);
            const float4* q = (const float4*)(s_qh + h * 64 + d0);
            float4 x0 = p[0], x1 = p[1];
            float4 q0 = q[0], q1 = q[1];
            float d = x0.x * q0.x + x0.y * q0.y + x0.z * q0.z + x0.w * q0.w
                    + x1.x * q1.x + x1.y * q1.y + x1.z * q1.z + x1.w * q1.w;
            d += __shfl_xor_sync(0xffffffffu, d, 1);
            d += __shfl_xor_sync(0xffffffffu, d, 2);
            d += __shfl_xor_sync(0xffffffffu, d, 4);
            if ((l & 7) == 0) s_ns[h][j] = d;
        }
        __syncwarp();
    }

    // scores + softmax
    {
        float sc = s_ns[h][l >> 1];
        const float4* ev = (const float4*)(&s_e[l][0]);
        const float4* we = (const float4*)(s_wf + h * 192);
#pragma unroll
        for (int j = 0; j < 16; j++) {
            float4 a = ev[j], b = we[j];
            sc += a.x * b.x + a.y * b.y + a.z * b.z + a.w * b.w;
        }
        const float4* tv = (const float4*)(&s_te[l][0]);
        const float4* wt = (const float4*)(s_wf + h * 192 + 64);
#pragma unroll
        for (int j = 0; j < 32; j++) {
            float4 a = tv[j], b = wt[j];
            sc += a.x * b.x + a.y * b.y + a.z * b.z + a.w * b.w;
        }
        sc *= 0.125f;
        float mx = sc;
        for (int o = 16; o; o >>= 1) mx = fmaxf(mx, __shfl_xor_sync(0xffffffffu, mx, o));
        float ex = expf(sc - mx);
        float sm = ex;
        for (int o = 16; o; o >>= 1) sm += __shfl_xor_sync(0xffffffffu, sm, o);
        float p = ex / sm;
        s_at[h][l] = p;
        float pp = p + __shfl_xor_sync(0xffffffffu, p, 1);
        if ((l & 1) == 0) s_a2[h][l >> 1] = pp;
    }
    __syncthreads();

    // ctx node part (fp32, consumed as accumulator-init by wmma5)
    {
        int j = tid * 2;
        int hh = j >> 6;
        unsigned long long acc = 0ull;
#pragma unroll 4
        for (int r = 0; r < 16; r++) {
            float2 v = *(const float2*)&g_proj[(long)s_idx[r] * 1536 + 512 + j];
            float a = s_a2[hh][r];
            ffma2(acc, pack2(a, a), pack2(v.x, v.y));
        }
        float o0, o1;
        unpack2(acc, o0, o1);
        *(float2*)&g_ctx[(long)n * 512 + j] = make_float2(o0, o1);
    }
    // ebar / tbar, float4 (4 columns per work item) -> bf16 [hi|lo|hi] per head
    for (int p = tid; p < 384; p += 256) {
        int hh = p / 48, c4 = (p % 48) * 4;
        unsigned long long acc0 = 0ull, acc1 = 0ull;
        if (c4 < 64) {
#pragma unroll
            for (int ll = 0; ll < 32; ll++) {
                float4 e = *(const float4*)&s_e[ll][c4];
                float a = s_at[hh][ll];
                unsigned long long a2 = pack2(a, a);
                ffma2(acc0, a2, pack2(e.x, e.y));
                ffma2(acc1, a2, pack2(e.z, e.w));
            }
        } else {
            int d = c4 - 64;
#pragma unroll
            for (int ll = 0; ll < 32; ll++) {
                float4 t4 = *(const float4*)&s_te[ll][d];
                float a = s_at[hh][ll];
                unsigned long long a2 = pack2(a, a);
                ffma2(acc0, a2, pack2(t4.x, t4.y));
                ffma2(acc1, a2, pack2(t4.z, t4.w));
            }
        }
        float o0, o1, o2, o3;
        unpack2(acc0, o0, o1);
        unpack2(acc1, o2, o3);
        float h0 = __bfloat162float(__float2bfloat16(o0));
        float h1 = __bfloat162float(__float2bfloat16(o1));
        float h2 = __bfloat162float(__float2bfloat16(o2));
        float h3 = __bfloat162float(__float2bfloat16(o3));
        uint2 hi4, lo4;
        hi4.x = bf2pack(o0, o1);       hi4.y = bf2pack(o2, o3);
        lo4.x = bf2pack(o0 - h0, o1 - h1);
        lo4.y = bf2pack(o2 - h2, o3 - h3);
        long base = ((long)n * 8 + hh) * 576;
        *(uint2*)&g_et3[base + c4]       = hi4;
        *(uint2*)&g_et3[base + 192 + c4] = lo4;
        *(uint2*)&g_et3[base + 384 + c4] = hi4;
    }
}

// ---------------- layernorm + concat (fc epilogue fused; writes split hcat) ----------
__global__ void ln_kernel(const float* __restrict__ lng, const float* __restrict__ lnb,
                          const float* __restrict__ nf,  const float* __restrict__ fcb)
{
    const int n = blockIdx.x, tid = threadIdx.x; // 128 threads
    float xv[3];
    int cnt = 0;
    float s = 0.f, sq = 0.f;
    for (int i = tid; i < 320; i += 128) {
        float v = g_x[(long)n * 320 + i] + fcb[i];
        if (i < 128)       v += nf[(long)n * 128 + i];
        else if (i >= 192) v += g_cosph[i - 192];
        xv[cnt++] = v;
        s += v; sq += v * v;
    }
    __shared__ float rs[4], rq[4];
    for (int o = 16; o; o >>= 1) {
        s  += __shfl_xor_sync(0xffffffffu, s,  o);
        sq += __shfl_xor_sync(0xffffffffu, sq, o);
    }
    int wid = tid >> 5, lane = tid & 31;
    if (lane == 0) { rs[wid] = s; rq[wid] = sq; }
    __syncthreads();
    float ts = rs[0] + rs[1] + rs[2] + rs[3];
    float tq = rq[0] + rq[1] + rq[2] + rq[3];
    float mu = ts * (1.f / 320.f);
    float var = tq * (1.f / 320.f) - mu * mu;
    float inv = rsqrtf(var + 1e-5f);
    long b = (long)n * 1344;
    cnt = 0;
    for (int i = tid; i < 320; i += 128) {
        float w = lng[i] * (xv[cnt++] - mu) * inv + lnb[i];
        int c = 128 + i;
        __nv_bfloat16 hi = __float2bfloat16(w);
        __nv_bfloat16 lo = __float2bfloat16(w - __bfloat162float(hi));
        g_hcat3[b + c] = hi;
        g_hcat3[b + 448 + c] = lo;
        g_hcat3[b + 896 + c] = hi;
    }
    {
        float w = nf[(long)n * 128 + tid];
        __nv_bfloat16 hi = __float2bfloat16(w);
        __nv_bfloat16 lo = __float2bfloat16(w - __bfloat162float(hi));
        g_hcat3[b + tid] = hi;
        g_hcat3[b + 448 + tid] = lo;
        g_hcat3[b + 896 + tid] = hi;
    }
}

// ---------------- launch ----------------
extern "C" void kernel_launch(void* const* d_in, const int* in_sizes, int n_in,
                              void* d_out, int out_size) {
    const float* nf   = (const float*)d_in[0];
    const float* ef   = (const float*)d_in[1];
    const float* dt   = (const float*)d_in[2];
    const int*   nidx = (const int*)  d_in[3];
    const float* freq = (const float*)d_in[4];
    const float* ph   = (const float*)d_in[5];
    const float* wqs  = (const float*)d_in[6];
    const float* wks  = (const float*)d_in[7];
    const float* wvs  = (const float*)d_in[8];
    const float* fcw  = (const float*)d_in[9];
    const float* fcb  = (const float*)d_in[10];
    const float* lng  = (const float*)d_in[11];
    const float* lnb  = (const float*)d_in[12];
    const float* nw   = (const float*)d_in[13];
    const float* nb   = (const float*)d_in[14];
    float* out = (float*)d_out;

    float *p_proj, *p_wfold, *p_ctx, *p_x, *p_biasq;
    __nv_bfloat16 *p_A3, *p_B3, *p_qh3, *p_wk3, *p_et3, *p_wv3, *p_ctx3, *p_fcw3, *p_hcat3, *p_nodew3;
    cudaGetSymbolAddress((void**)&p_proj,   g_proj);
    cudaGetSymbolAddress((void**)&p_wfold,  g_wfold);
    cudaGetSymbolAddress((void**)&p_ctx,    g_ctx);
    cudaGetSymbolAddress((void**)&p_x,      g_x);
    cudaGetSymbolAddress((void**)&p_biasq,  g_biasq);
    cudaGetSymbolAddress((void**)&p_A3,     g_A3);
    cudaGetSymbolAddress((void**)&p_B3,     g_B3);
    cudaGetSymbolAddress((void**)&p_qh3,    g_qh3);
    cudaGetSymbolAddress((void**)&p_wk3,    g_wk3);
    cudaGetSymbolAddress((void**)&p_et3,    g_et3);
    cudaGetSymbolAddress((void**)&p_wv3,    g_wv3);
    cudaGetSymbolAddress((void**)&p_ctx3,   g_ctx3);
    cudaGetSymbolAddress((void**)&p_fcw3,   g_fcw3);
    cudaGetSymbolAddress((void**)&p_hcat3,  g_hcat3);
    cudaGetSymbolAddress((void**)&p_nodew3, g_nodew3);

    // 1) weight splits + biasq + cosph; 2) input split
    prep_kernel<<<(1843840 + 255) / 256, 256>>>(wks, wvs, wqs, fcw, nw, ph);
    convA_kernel<<<(N_SRC * 128 + 255) / 256, 256>>>(nf);

    // 3) node_k|node_v|qh projection (tensor), qh-bias + qh3 split fused in epilogue;
    //    dead qh blocks (rows >= N_DST) early-exit
    wmma_gemm<128,128,4><<<dim3(12, 128), 256>>>(p_A3, p_B3, p_proj, 384, 384, 384, 1536,
                                                 0, 0, 0, p_biasq, p_qh3);

    // 4) fold q into K-weights (tensor, batched per head)  [profiled launch]
    wmma_gemm<128,64,0><<<dim3(3, 64, 8), 256>>>(p_qh3, p_wk3, p_wfold, 192, 1536, 192, 1536,
                                                 192, (long)192 * 192, 192, nullptr, nullptr);

    // 5) fused attention per dst (writes g_ctx fp32 + g_et3 split)
    attn_kernel<<<N_DST, 256>>>(ef, dt, nidx, freq, ph);

    // 6) V projection (tensor, batched, accumulate onto ctx, emit ctx3 split)
    wmma_gemm<128,64,2><<<dim3(1, 64, 8), 256>>>(p_et3, p_wv3, p_ctx, 576, 4608, 576, 512,
                                                 576, (long)64 * 576, 64, nullptr, p_ctx3);

    // 7) fc (tensor): 8192x320, K'=1536; epilogue fused in ln
    wmma_gemm<128,64,0><<<dim3(5, 64), 256>>>(p_ctx3, p_fcw3, p_x, 1536, 1536, 1536, 320,
                                              0, 0, 0, nullptr, nullptr);

    // 8) layernorm + concat (writes split hcat)
    ln_kernel<<<N_DST, 128>>>(lng, lnb, nf, fcb);

    // 9) final (tensor), bias+relu fused, writes out directly
    wmma_gemm<128,64,3><<<dim3(2, 64), 256>>>(p_hcat3, p_nodew3, out, 1344, 1344, 1344, 128,
                                              0, 0, 0, nb, nullptr);
}

// round 16
// speedup vs baseline: 1.1591x; 1.0232x over previous
#include <cuda_runtime.h>
#include <cuda_bf16.h>
#include <mma.h>
#include <math.h>

using namespace nvcuda;

#define N_SRC   16384
#define N_DST   8192

// ---------------- scratch (device globals; no allocations) ----------------
__device__ float g_proj[(long)N_SRC * 1536];   // [0:512) node_k | [512:1024) node_v | [1024:1536) qh
__device__ float g_biasq[512];
__device__ float g_cosph[128];
__device__ float g_wfold[(long)N_DST * 1536];
__device__ float g_ctx[(long)N_DST * 512];
__device__ float g_x[(long)N_DST * 320];
// bf16-split A-operands: logical [hi|lo|hi]; seg2 NOT stored (loader remaps seg2->seg0).
// B-operands keep full 3-segment [hi|hi|lo] storage.
__device__ __nv_bfloat16 g_A3[(long)N_SRC * 384];     // only [0:256) per row used
__device__ __nv_bfloat16 g_B3[(long)1536 * 384];
__device__ __nv_bfloat16 g_qh3[(long)N_DST * 1536];   // per head: only [0:128) used
__device__ __nv_bfloat16 g_wk3[8 * 192 * 192];
__device__ __nv_bfloat16 g_et3[(long)N_DST * 4608];   // per head: only [0:384) used
__device__ __nv_bfloat16 g_wv3[8 * 64 * 576];
__device__ __nv_bfloat16 g_ctx3[(long)N_DST * 1536];  // only [0:1024) per row used
__device__ __nv_bfloat16 g_fcw3[(long)320 * 1536];
__device__ __nv_bfloat16 g_hcat3[(long)N_DST * 1344]; // only [0:896) per row used
__device__ __nv_bfloat16 g_nodew3[(long)128 * 1344];

// ---------------- helpers ----------------
__device__ __forceinline__ unsigned long long pack2(float x, float y) {
    unsigned long long r;
    asm("mov.b64 %0, {%1, %2};" : "=l"(r) : "f"(x), "f"(y));
    return r;
}
__device__ __forceinline__ void unpack2(unsigned long long v, float& x, float& y) {
    asm("mov.b64 {%0, %1}, %2;" : "=f"(x), "=f"(y) : "l"(v));
}
__device__ __forceinline__ void ffma2(unsigned long long& d, unsigned long long a, unsigned long long b) {
    asm("fma.rn.f32x2 %0, %1, %2, %0;" : "+l"(d) : "l"(a), "l"(b));
}
__device__ __forceinline__ __nv_bfloat16 bsplit(float v, int is_lo) {
    __nv_bfloat16 h = __float2bfloat16(v);
    if (!is_lo) return h;
    return __float2bfloat16(v - __bfloat162float(h));
}
__device__ __forceinline__ unsigned int bf2pack(float a, float b) {
    __nv_bfloat162 t;
    t.x = __float2bfloat16(a);
    t.y = __float2bfloat16(b);
    return *(unsigned int*)&t;
}
__device__ __forceinline__ void cp16(unsigned int saddr, const void* gptr) {
    asm volatile("cp.async.cg.shared.global [%0], [%1], 16;" :: "r"(saddr), "l"(gptr) : "memory");
}
__device__ __forceinline__ void cp_commit() {
    asm volatile("cp.async.commit_group;" ::: "memory");
}
template<int N>
__device__ __forceinline__ void cp_wait() {
    asm volatile("cp.async.wait_group %0;" :: "n"(N) : "memory");
}

// ---------------- prep: weight splits + biasq + cosph + A3 input split -------------
__global__ void prep_kernel(const float* __restrict__ wks, const float* __restrict__ wvs,
                            const float* __restrict__ wqs, const float* __restrict__ fcw,
                            const float* __restrict__ nw,  const float* __restrict__ ph,
                            const float* __restrict__ nf)
{
    const int S0 = 589824;             // B3: 1536 x 384
    const int S1 = S0 + 294912;        // wk3: 8 x 192 x 192
    const int S2 = S1 + 294912;        // wv3: 8 x 64 x 576
    const int S3 = S2 + 491520;        // fcw3: 320 x 1536
    const int S4 = S3 + 172032;        // nodew3: 128 x 1344
    const int S5 = S4 + 512;           // biasq
    const int S6 = S5 + 128;           // cosph
    const int S7 = S6 + N_SRC * 128;   // A3 split (hi+lo only)
    int t = blockIdx.x * blockDim.x + threadIdx.x;
    if (t < S0) {
        int r = t / 384, kp = t % 384;
        int k = kp & 127, seg = kp >> 7;
        float v;
        if (r < 512)       v = wks[r * 320 + k];
        else if (r < 1024) v = wvs[(r - 512) * 320 + k];
        else               v = wqs[(r - 1024) * 320 + k];
        g_B3[t] = bsplit(v, seg == 2);
    } else if (t < S1) {
        int i = t - S0;
        int h = i / 36864, rem = i % 36864;
        int c = rem / 192, kp = rem % 192;
        int d = kp & 63, seg = kp >> 6;
        float v = wks[(h * 64 + d) * 320 + 128 + c];
        g_wk3[i] = bsplit(v, seg == 2);
    } else if (t < S2) {
        int i = t - S1;
        int h = i / 36864, rem = i % 36864;
        int d = rem / 576, kp = rem % 576;
        int c = kp % 192, seg = kp / 192;
        float v = wvs[(h * 64 + d) * 320 + 128 + c];
        g_wv3[i] = bsplit(v, seg == 2);
    } else if (t < S3) {
        int i = t - S2;
        int c = i / 1536, kp = i % 1536;
        int j = kp & 511, seg = kp >> 9;
        float v = fcw[c * 512 + j];
        g_fcw3[i] = bsplit(v, seg == 2);
    } else if (t < S4) {
        int i = t - S3;
        int o = i / 1344, kp = i % 1344;
        int c = kp % 448, seg = kp / 448;
        float v = nw[o * 448 + c];
        g_nodew3[i] = bsplit(v, seg == 2);
    } else if (t < S5) {
        int j = t - S4;
        float acc = 0.f;
        for (int d = 0; d < 128; d++) acc += cosf(ph[d]) * wqs[j * 320 + 192 + d];
        g_biasq[j] = acc;
    } else if (t < S6) {
        g_cosph[t - S5] = cosf(ph[t - S5]);
    } else if (t < S7) {
        int i = t - S6;
        int m = i >> 7, k = i & 127;
        float v = nf[i];
        __nv_bfloat16 hi = __float2bfloat16(v);
        __nv_bfloat16 lo = __float2bfloat16(v - __bfloat162float(hi));
        long b = (long)m * 384;
        g_A3[b + k] = hi;
        g_A3[b + 128 + k] = lo;
        // seg2 (dup of hi) intentionally NOT stored — loader remaps
    }
}

// ---------------- bf16 wmma GEMM, BK=64, cp.async 2-stage smem pipeline ------------
// A side: logical K3 = 3*SEG, stored [hi|lo]; loader remaps k0>=2*SEG -> k0-2*SEG.
// B side: full 3-segment storage, no remap.
// EPI: 0 plain store;
//      2 accumulate(init from C) -> also write bf16 [hi|lo] to aux_bf (ctx3 layout);
//      3 relu(v + aux_f[col]) -> store to C;
//      4 plain store + fused qh epilogue (tiles with tn0>=1024 && tm0<N_DST);
//        blocks with tn0>=1024 && tm0>=N_DST early-exit.
template<int BM, int BN, int EPI, int SEG>
__global__ void wmma_gemm(const __nv_bfloat16* __restrict__ A,
                          const __nv_bfloat16* __restrict__ Bt,
                          float* __restrict__ C,
                          int K3, int lda, int ldb, int ldc,
                          long bsA, long bsB, long bsC,
                          const float* __restrict__ aux_f,
                          __nv_bfloat16* __restrict__ aux_bf)
{
    constexpr int BK = 64;
    constexpr int PAD = 8;
    constexpr int LDSH = BK + PAD;
    constexpr int CPR = BK / 8;                 // 16B chunks per row
    constexpr int FR_M = BM / 64;
    constexpr int FR_N = BN / 32;
    constexpr int A_LD = BM * CPR / 256;
    constexpr int B_LD = BN * CPR / 256;
    __shared__ __align__(16) __nv_bfloat16 sbuf[2][(BM + BN) * LDSH];
    const int bz = blockIdx.z;
    A += (long)bz * bsA; Bt += (long)bz * bsB; C += (long)bz * bsC;
    const int tid = threadIdx.x;
    const int wid = tid >> 5;
    const int wm = wid & 3;
    const int wn = wid >> 2;
    const int tm0 = blockIdx.y * BM;
    const int tn0 = blockIdx.x * BN;

    // qh columns are only consumed for rows < N_DST — skip dead blocks entirely
    if (EPI == 4 && tn0 >= 1024 && tm0 >= N_DST) return;

    wmma::fragment<wmma::accumulator, 16, 16, 16, float> cf[FR_M][FR_N];
#pragma unroll
    for (int i = 0; i < FR_M; i++)
#pragma unroll
        for (int j = 0; j < FR_N; j++) {
            if (EPI == 2)
                wmma::load_matrix_sync(cf[i][j],
                    &C[(long)(tm0 + wm * 32 + i * 16) * ldc + tn0 + wn * (BN / 2) + j * 16],
                    ldc, wmma::mem_row_major);
            else
                wmma::fill_fragment(cf[i][j], 0.f);
        }

    auto loadStage = [&](int st, int k0) {
        int ka = (k0 >= 2 * SEG) ? k0 - 2 * SEG : k0;   // A: seg2 aliases seg0
#pragma unroll
        for (int it = 0; it < A_LD; it++) {
            int idx = tid + it * 256;
            int r = idx / CPR, c8 = idx % CPR;
            cp16((unsigned int)__cvta_generic_to_shared(&sbuf[st][r * LDSH + c8 * 8]),
                 &A[(long)(tm0 + r) * lda + ka + c8 * 8]);
        }
#pragma unroll
        for (int it = 0; it < B_LD; it++) {
            int idx = tid + it * 256;
            int r = idx / CPR, c8 = idx % CPR;
            cp16((unsigned int)__cvta_generic_to_shared(&sbuf[st][(BM + r) * LDSH + c8 * 8]),
                 &Bt[(long)(tn0 + r) * ldb + k0 + c8 * 8]);
        }
        cp_commit();
    };

    const int nIter = K3 / BK;
    loadStage(0, 0);
    for (int it = 0; it < nIter; it++) {
        int st = it & 1;
        if (it + 1 < nIter) {
            loadStage(st ^ 1, (it + 1) * BK);
            cp_wait<1>();
        } else {
            cp_wait<0>();
        }
        __syncthreads();
#pragma unroll
        for (int kk = 0; kk < BK; kk += 16) {
            wmma::fragment<wmma::matrix_a, 16, 16, 16, __nv_bfloat16, wmma::row_major> af[FR_M];
            wmma::fragment<wmma::matrix_b, 16, 16, 16, __nv_bfloat16, wmma::col_major> bf[FR_N];
#pragma unroll
            for (int i = 0; i < FR_M; i++)
                wmma::load_matrix_sync(af[i], &sbuf[st][(wm * 32 + i * 16) * LDSH + kk], LDSH);
#pragma unroll
            for (int j = 0; j < FR_N; j++)
                wmma::load_matrix_sync(bf[j], &sbuf[st][(BM + wn * (BN / 2) + j * 16) * LDSH + kk], LDSH);
#pragma unroll
            for (int i = 0; i < FR_M; i++)
#pragma unroll
                for (int j = 0; j < FR_N; j++)
                    wmma::mma_sync(cf[i][j], af[i], bf[j], cf[i][j]);
        }
        __syncthreads();
    }

    if (EPI == 0 || EPI == 4) {
#pragma unroll
        for (int i = 0; i < FR_M; i++)
#pragma unroll
            for (int j = 0; j < FR_N; j++)
                wmma::store_matrix_sync(&C[(long)(tm0 + wm * 32 + i * 16) * ldc + tn0 + wn * (BN / 2) + j * 16],
                                        cf[i][j], ldc, wmma::mem_row_major);
        if (EPI == 4) {
            __syncthreads();
            if (tn0 >= 1024 && tm0 < N_DST) {
                for (int idx = tid; idx < BM * BN; idx += 256) {
                    int r = idx / BN, c = idx % BN;
                    int row = tm0 + r;
                    if (row < N_DST) {
                        int col = tn0 + c;
                        long off = (long)row * ldc + col;
                        int j = col - 1024;
                        float v = C[off] + aux_f[j];
                        C[off] = v;
                        int h = j >> 6, d = j & 63;
                        __nv_bfloat16 hi = __float2bfloat16(v);
                        __nv_bfloat16 lo = __float2bfloat16(v - __bfloat162float(hi));
                        long b = (long)row * 1536 + h * 192;
                        aux_bf[b + d] = hi;
                        aux_bf[b + 64 + d] = lo;
                        // seg2 dup not stored — wmma4 loader remaps
                    }
                }
            }
        }
    } else {
        // stage fp32 tile in shared (aliasing the dead pipeline buffers)
        float* sC = (float*)&sbuf[0][0];
        static_assert(sizeof(sbuf) >= BM * BN * sizeof(float) || EPI == 0 || EPI == 4, "sC alias too small");
#pragma unroll
        for (int i = 0; i < FR_M; i++)
#pragma unroll
            for (int j = 0; j < FR_N; j++)
                wmma::store_matrix_sync(&sC[(wm * 32 + i * 16) * BN + wn * (BN / 2) + j * 16],
                                        cf[i][j], BN, wmma::mem_row_major);
        __syncthreads();
        for (int idx = tid; idx < BM * BN; idx += 256) {
            int r = idx / BN, c = idx % BN;
            float v = sC[idx];
            int row = tm0 + r;
            if (EPI == 2) {
                int j = bz * 64 + tn0 + c;
                __nv_bfloat16 hi = __float2bfloat16(v);
                __nv_bfloat16 lo = __float2bfloat16(v - __bfloat162float(hi));
                long b = (long)row * 1536 + j;
                aux_bf[b] = hi;
                aux_bf[b + 512] = lo;
                // seg2 dup not stored — wmma7 loader remaps
            }
            if (EPI == 3) {
                int col = tn0 + c;
                C[(long)row * ldc + col] = fmaxf(v + aux_f[col], 0.f);
            }
        }
    }
}

// ---------------- fused attention kernel: one block per dst node ----------------
__global__ void attn_kernel(const float* __restrict__ ef, const float* __restrict__ dt,
                            const int* __restrict__ nidx,
                            const float* __restrict__ freq, const float* __restrict__ ph)
{
    const int n = blockIdx.x;
    const int tid = threadIdx.x;
    __shared__ __align__(16) float s_qh[512];
    __shared__ __align__(16) float s_wf[1536];
    __shared__ __align__(16) float s_te[32][132];
    __shared__ __align__(16) float s_e[32][68];
    __shared__ float s_dt[32];
    __shared__ int   s_idx[16];
    __shared__ float s_fr[128], s_ph[128];
    __shared__ float s_at[8][33];
    __shared__ float s_a2[8][17];
    __shared__ float s_ns[8][17];

    for (int i = tid; i < 512;  i += 256) s_qh[i] = g_proj[(long)n * 1536 + 1024 + i];
    for (int i = tid; i < 1536; i += 256) s_wf[i] = g_wfold[(long)n * 1536 + i];
    {
        const float4* ef4 = (const float4*)(ef + (long)n * 2048);
        for (int i = tid; i < 512; i += 256) {
            int l = i >> 4, c4 = i & 15;
            *(float4*)&s_e[l][c4 * 4] = ef4[i];
        }
    }
    if (tid < 128) { s_fr[tid] = freq[tid]; s_ph[tid] = ph[tid]; }
    if (tid < 32)  s_dt[tid] = dt[(long)n * 32 + tid];
    if (tid < 16)  s_idx[tid] = nidx[n * 16 + tid];
    __syncthreads();

    // temporal encoding via hardware cos (MUFU pipe)
    for (int i = tid; i < 4096; i += 256) {
        int l = i >> 7, d = i & 127;
        s_te[l][d] = __cosf(fmaf(s_dt[l], s_fr[d], s_ph[d]));
    }
    __syncthreads();

    const int h = tid >> 5, l = tid & 31;

    // node scores (16 distinct neighbors, coalesced)
    {
#pragma unroll
        for (int jb = 0; jb < 16; jb += 4) {
            int j = jb + (l >> 3);
            int d0 = (l & 7) * 8;
            const float4* p = (const float4*)(g_proj + (long)s_idx[j] * 1536 + h * 64 + d0);
            const float4* q = (const float4*)(s_qh + h * 64 + d0);
            float4 x0 = p[0], x1 = p[1];
            float4 q0 = q[0], q1 = q[1];
            float d = x0.x * q0.x + x0.y * q0.y + x0.z * q0.z + x0.w * q0.w
                    + x1.x * q1.x + x1.y * q1.y + x1.z * q1.z + x1.w * q1.w;
            d += __shfl_xor_sync(0xffffffffu, d, 1);
            d += __shfl_xor_sync(0xffffffffu, d, 2);
            d += __shfl_xor_sync(0xffffffffu, d, 4);
            if ((l & 7) == 0) s_ns[h][j] = d;
        }
        __syncwarp();
    }

    // scores + softmax
    {
        float sc = s_ns[h][l >> 1];
        const float4* ev = (const float4*)(&s_e[l][0]);
        const float4* we = (const float4*)(s_wf + h * 192);
#pragma unroll
        for (int j = 0; j < 16; j++) {
            float4 a = ev[j], b = we[j];
            sc += a.x * b.x + a.y * b.y + a.z * b.z + a.w * b.w;
        }
        const float4* tv = (const float4*)(&s_te[l][0]);
        const float4* wt = (const float4*)(s_wf + h * 192 + 64);
#pragma unroll
        for (int j = 0; j < 32; j++) {
            float4 a = tv[j], b = wt[j];
            sc += a.x * b.x + a.y * b.y + a.z * b.z + a.w * b.w;
        }
        sc *= 0.125f;
        float mx = sc;
        for (int o = 16; o; o >>= 1) mx = fmaxf(mx, __shfl_xor_sync(0xffffffffu, mx, o));
        float ex = expf(sc - mx);
        float sm = ex;
        for (int o = 16; o; o >>= 1) sm += __shfl_xor_sync(0xffffffffu, sm, o);
        float p = ex / sm;
        s_at[h][l] = p;
        float pp = p + __shfl_xor_sync(0xffffffffu, p, 1);
        if ((l & 1) == 0) s_a2[h][l >> 1] = pp;
    }
    __syncthreads();

    // ctx node part (fp32, consumed as accumulator-init by wmma5)
    {
        int j = tid * 2;
        int hh = j >> 6;
        unsigned long long acc = 0ull;
#pragma unroll 4
        for (int r = 0; r < 16; r++) {
            float2 v = *(const float2*)&g_proj[(long)s_idx[r] * 1536 + 512 + j];
            float a = s_a2[hh][r];
            ffma2(acc, pack2(a, a), pack2(v.x, v.y));
        }
        float o0, o1;
        unpack2(acc, o0, o1);
        *(float2*)&g_ctx[(long)n * 512 + j] = make_float2(o0, o1);
    }
    // ebar / tbar, float4 -> bf16 [hi|lo] per head (seg2 dup not stored)
    for (int p = tid; p < 384; p += 256) {
        int hh = p / 48, c4 = (p % 48) * 4;
        unsigned long long acc0 = 0ull, acc1 = 0ull;
        if (c4 < 64) {
#pragma unroll
            for (int ll = 0; ll < 32; ll++) {
                float4 e = *(const float4*)&s_e[ll][c4];
                float a = s_at[hh][ll];
                unsigned long long a2 = pack2(a, a);
                ffma2(acc0, a2, pack2(e.x, e.y));
                ffma2(acc1, a2, pack2(e.z, e.w));
            }
        } else {
            int d = c4 - 64;
#pragma unroll
            for (int ll = 0; ll < 32; ll++) {
                float4 t4 = *(const float4*)&s_te[ll][d];
                float a = s_at[hh][ll];
                unsigned long long a2 = pack2(a, a);
                ffma2(acc0, a2, pack2(t4.x, t4.y));
                ffma2(acc1, a2, pack2(t4.z, t4.w));
            }
        }
        float o0, o1, o2, o3;
        unpack2(acc0, o0, o1);
        unpack2(acc1, o2, o3);
        float h0 = __bfloat162float(__float2bfloat16(o0));
        float h1 = __bfloat162float(__float2bfloat16(o1));
        float h2 = __bfloat162float(__float2bfloat16(o2));
        float h3 = __bfloat162float(__float2bfloat16(o3));
        uint2 hi4, lo4;
        hi4.x = bf2pack(o0, o1);       hi4.y = bf2pack(o2, o3);
        lo4.x = bf2pack(o0 - h0, o1 - h1);
        lo4.y = bf2pack(o2 - h2, o3 - h3);
        long base = ((long)n * 8 + hh) * 576;
        *(uint2*)&g_et3[base + c4]       = hi4;
        *(uint2*)&g_et3[base + 192 + c4] = lo4;
        // seg2 dup not stored — wmma5 loader remaps
    }
}

// ---------------- layernorm + concat (fc epilogue fused; writes [hi|lo] hcat) -------
__global__ void ln_kernel(const float* __restrict__ lng, const float* __restrict__ lnb,
                          const float* __restrict__ nf,  const float* __restrict__ fcb)
{
    const int n = blockIdx.x, tid = threadIdx.x; // 128 threads
    float xv[3];
    int cnt = 0;
    float s = 0.f, sq = 0.f;
    for (int i = tid; i < 320; i += 128) {
        float v = g_x[(long)n * 320 + i] + fcb[i];
        if (i < 128)       v += nf[(long)n * 128 + i];
        else if (i >= 192) v += g_cosph[i - 192];
        xv[cnt++] = v;
        s += v; sq += v * v;
    }
    __shared__ float rs[4], rq[4];
    for (int o = 16; o; o >>= 1) {
        s  += __shfl_xor_sync(0xffffffffu, s,  o);
        sq += __shfl_xor_sync(0xffffffffu, sq, o);
    }
    int wid = tid >> 5, lane = tid & 31;
    if (lane == 0) { rs[wid] = s; rq[wid] = sq; }
    __syncthreads();
    float ts = rs[0] + rs[1] + rs[2] + rs[3];
    float tq = rq[0] + rq[1] + rq[2] + rq[3];
    float mu = ts * (1.f / 320.f);
    float var = tq * (1.f / 320.f) - mu * mu;
    float inv = rsqrtf(var + 1e-5f);
    long b = (long)n * 1344;
    cnt = 0;
    for (int i = tid; i < 320; i += 128) {
        float w = lng[i] * (xv[cnt++] - mu) * inv + lnb[i];
        int c = 128 + i;
        __nv_bfloat16 hi = __float2bfloat16(w);
        __nv_bfloat16 lo = __float2bfloat16(w - __bfloat162float(hi));
        g_hcat3[b + c] = hi;
        g_hcat3[b + 448 + c] = lo;
        // seg2 dup not stored — wmma9 loader remaps
    }
    {
        float w = nf[(long)n * 128 + tid];
        __nv_bfloat16 hi = __float2bfloat16(w);
        __nv_bfloat16 lo = __float2bfloat16(w - __bfloat162float(hi));
        g_hcat3[b + tid] = hi;
        g_hcat3[b + 448 + tid] = lo;
    }
}

// ---------------- launch ----------------
extern "C" void kernel_launch(void* const* d_in, const int* in_sizes, int n_in,
                              void* d_out, int out_size) {
    const float* nf   = (const float*)d_in[0];
    const float* ef   = (const float*)d_in[1];
    const float* dt   = (const float*)d_in[2];
    const int*   nidx = (const int*)  d_in[3];
    const float* freq = (const float*)d_in[4];
    const float* ph   = (const float*)d_in[5];
    const float* wqs  = (const float*)d_in[6];
    const float* wks  = (const float*)d_in[7];
    const float* wvs  = (const float*)d_in[8];
    const float* fcw  = (const float*)d_in[9];
    const float* fcb  = (const float*)d_in[10];
    const float* lng  = (const float*)d_in[11];
    const float* lnb  = (const float*)d_in[12];
    const float* nw   = (const float*)d_in[13];
    const float* nb   = (const float*)d_in[14];
    float* out = (float*)d_out;

    float *p_proj, *p_wfold, *p_ctx, *p_x, *p_biasq;
    __nv_bfloat16 *p_A3, *p_B3, *p_qh3, *p_wk3, *p_et3, *p_wv3, *p_ctx3, *p_fcw3, *p_hcat3, *p_nodew3;
    cudaGetSymbolAddress((void**)&p_proj,   g_proj);
    cudaGetSymbolAddress((void**)&p_wfold,  g_wfold);
    cudaGetSymbolAddress((void**)&p_ctx,    g_ctx);
    cudaGetSymbolAddress((void**)&p_x,      g_x);
    cudaGetSymbolAddress((void**)&p_biasq,  g_biasq);
    cudaGetSymbolAddress((void**)&p_A3,     g_A3);
    cudaGetSymbolAddress((void**)&p_B3,     g_B3);
    cudaGetSymbolAddress((void**)&p_qh3,    g_qh3);
    cudaGetSymbolAddress((void**)&p_wk3,    g_wk3);
    cudaGetSymbolAddress((void**)&p_et3,    g_et3);
    cudaGetSymbolAddress((void**)&p_wv3,    g_wv3);
    cudaGetSymbolAddress((void**)&p_ctx3,   g_ctx3);
    cudaGetSymbolAddress((void**)&p_fcw3,   g_fcw3);
    cudaGetSymbolAddress((void**)&p_hcat3,  g_hcat3);
    cudaGetSymbolAddress((void**)&p_nodew3, g_nodew3);

    // 1) weight splits + biasq + cosph + A3 input split (merged)
    const int PREP_TOTAL = 1843840 + N_SRC * 128;
    prep_kernel<<<(PREP_TOTAL + 255) / 256, 256>>>(wks, wvs, wqs, fcw, nw, ph, nf);

    // 2) node_k|node_v|qh projection (tensor), qh-bias + qh3 split fused;
    //    dead qh blocks early-exit; A seg2 remapped
    wmma_gemm<128,128,4,128><<<dim3(12, 128), 256>>>(p_A3, p_B3, p_proj, 384, 384, 384, 1536,
                                                     0, 0, 0, p_biasq, p_qh3);

    // 3) fold q into K-weights (tensor, batched per head)
    wmma_gemm<128,64,0,64><<<dim3(3, 64, 8), 256>>>(p_qh3, p_wk3, p_wfold, 192, 1536, 192, 1536,
                                                    192, (long)192 * 192, 192, nullptr, nullptr);

    // 4) fused attention per dst (writes g_ctx fp32 + g_et3 [hi|lo])
    attn_kernel<<<N_DST, 256>>>(ef, dt, nidx, freq, ph);

    // 5) V projection (tensor, batched, accumulate onto ctx, emit ctx3 [hi|lo])
    wmma_gemm<128,64,2,192><<<dim3(1, 64, 8), 256>>>(p_et3, p_wv3, p_ctx, 576, 4608, 576, 512,
                                                     576, (long)64 * 576, 64, nullptr, p_ctx3);

    // 6) fc (tensor): 8192x320, K'=1536; epilogue fused in ln
    wmma_gemm<128,64,0,512><<<dim3(5, 64), 256>>>(p_ctx3, p_fcw3, p_x, 1536, 1536, 1536, 320,
                                                  0, 0, 0, nullptr, nullptr);

    // 7) layernorm + concat (writes [hi|lo] hcat)
    ln_kernel<<<N_DST, 128>>>(lng, lnb, nf, fcb);

    // 8) final (tensor), bias+relu fused, writes out directly
    wmma_gemm<128,64,3,448><<<dim3(2, 64), 256>>>(p_hcat3, p_nodew3, out, 1344, 1344, 1344, 128,
                                                  0, 0, 0, nb, nullptr);
}

// round 17
// speedup vs baseline: 1.2121x; 1.0458x over previous
#include <cuda_runtime.h>
#include <cuda_bf16.h>
#include <mma.h>
#include <math.h>

using namespace nvcuda;

#define N_SRC   16384
#define N_DST   8192

// ---------------- scratch (device globals; no allocations) ----------------
__device__ float g_proj[(long)N_SRC * 1536];   // [0:512) node_k | [512:1024) node_v | [1024:1536) qh
__device__ float g_biasq[512];
__device__ float g_cosph[128];
__device__ float g_wfold[(long)N_DST * 1536];
__device__ float g_ctx[(long)N_DST * 512];
__device__ float g_x[(long)N_DST * 320];
// bf16-split A-operands: logical [hi|lo|hi]; seg2 NOT stored (loader remaps seg2->seg0).
// B-operands keep full 3-segment [hi|hi|lo] storage.
__device__ __nv_bfloat16 g_A3[(long)N_SRC * 384];     // only [0:256) per row used
__device__ __nv_bfloat16 g_B3[(long)1536 * 384];
__device__ __nv_bfloat16 g_qh3[(long)N_DST * 1536];   // per head: only [0:128) used
__device__ __nv_bfloat16 g_wk3[8 * 192 * 192];
__device__ __nv_bfloat16 g_et3[(long)N_DST * 4608];   // per head: only [0:384) used
__device__ __nv_bfloat16 g_wv3[8 * 64 * 576];
__device__ __nv_bfloat16 g_ctx3[(long)N_DST * 1536];  // only [0:1024) per row used
__device__ __nv_bfloat16 g_fcw3[(long)320 * 1536];
__device__ __nv_bfloat16 g_hcat3[(long)N_DST * 1344]; // only [0:896) per row used
__device__ __nv_bfloat16 g_nodew3[(long)128 * 1344];

// ---------------- helpers ----------------
__device__ __forceinline__ unsigned long long pack2(float x, float y) {
    unsigned long long r;
    asm("mov.b64 %0, {%1, %2};" : "=l"(r) : "f"(x), "f"(y));
    return r;
}
__device__ __forceinline__ void unpack2(unsigned long long v, float& x, float& y) {
    asm("mov.b64 {%0, %1}, %2;" : "=f"(x), "=f"(y) : "l"(v));
}
__device__ __forceinline__ void ffma2(unsigned long long& d, unsigned long long a, unsigned long long b) {
    asm("fma.rn.f32x2 %0, %1, %2, %0;" : "+l"(d) : "l"(a), "l"(b));
}
__device__ __forceinline__ __nv_bfloat16 bsplit(float v, int is_lo) {
    __nv_bfloat16 h = __float2bfloat16(v);
    if (!is_lo) return h;
    return __float2bfloat16(v - __bfloat162float(h));
}
__device__ __forceinline__ unsigned int bf2pack(float a, float b) {
    __nv_bfloat162 t;
    t.x = __float2bfloat16(a);
    t.y = __float2bfloat16(b);
    return *(unsigned int*)&t;
}
__device__ __forceinline__ void cp16(unsigned int saddr, const void* gptr) {
    asm volatile("cp.async.cg.shared.global [%0], [%1], 16;" :: "r"(saddr), "l"(gptr) : "memory");
}
__device__ __forceinline__ void cp_commit() {
    asm volatile("cp.async.commit_group;" ::: "memory");
}
template<int N>
__device__ __forceinline__ void cp_wait() {
    asm volatile("cp.async.wait_group %0;" :: "n"(N) : "memory");
}

// ---------------- prep: weight splits + biasq + cosph + A3 input split -------------
__global__ void prep_kernel(const float* __restrict__ wks, const float* __restrict__ wvs,
                            const float* __restrict__ wqs, const float* __restrict__ fcw,
                            const float* __restrict__ nw,  const float* __restrict__ ph,
                            const float* __restrict__ nf)
{
    const int S0 = 589824;             // B3: 1536 x 384
    const int S1 = S0 + 294912;        // wk3: 8 x 192 x 192
    const int S2 = S1 + 294912;        // wv3: 8 x 64 x 576
    const int S3 = S2 + 491520;        // fcw3: 320 x 1536
    const int S4 = S3 + 172032;        // nodew3: 128 x 1344
    const int S5 = S4 + 512;           // biasq
    const int S6 = S5 + 128;           // cosph
    const int S7 = S6 + N_SRC * 128;   // A3 split (hi+lo only)
    int t = blockIdx.x * blockDim.x + threadIdx.x;
    if (t < S0) {
        int r = t / 384, kp = t % 384;
        int k = kp & 127, seg = kp >> 7;
        float v;
        if (r < 512)       v = wks[r * 320 + k];
        else if (r < 1024) v = wvs[(r - 512) * 320 + k];
        else               v = wqs[(r - 1024) * 320 + k];
        g_B3[t] = bsplit(v, seg == 2);
    } else if (t < S1) {
        int i = t - S0;
        int h = i / 36864, rem = i % 36864;
        int c = rem / 192, kp = rem % 192;
        int d = kp & 63, seg = kp >> 6;
        float v = wks[(h * 64 + d) * 320 + 128 + c];
        g_wk3[i] = bsplit(v, seg == 2);
    } else if (t < S2) {
        int i = t - S1;
        int h = i / 36864, rem = i % 36864;
        int d = rem / 576, kp = rem % 576;
        int c = kp % 192, seg = kp / 192;
        float v = wvs[(h * 64 + d) * 320 + 128 + c];
        g_wv3[i] = bsplit(v, seg == 2);
    } else if (t < S3) {
        int i = t - S2;
        int c = i / 1536, kp = i % 1536;
        int j = kp & 511, seg = kp >> 9;
        float v = fcw[c * 512 + j];
        g_fcw3[i] = bsplit(v, seg == 2);
    } else if (t < S4) {
        int i = t - S3;
        int o = i / 1344, kp = i % 1344;
        int c = kp % 448, seg = kp / 448;
        float v = nw[o * 448 + c];
        g_nodew3[i] = bsplit(v, seg == 2);
    } else if (t < S5) {
        int j = t - S4;
        float acc = 0.f;
        for (int d = 0; d < 128; d++) acc += cosf(ph[d]) * wqs[j * 320 + 192 + d];
        g_biasq[j] = acc;
    } else if (t < S6) {
        g_cosph[t - S5] = cosf(ph[t - S5]);
    } else if (t < S7) {
        int i = t - S6;
        int m = i >> 7, k = i & 127;
        float v = nf[i];
        __nv_bfloat16 hi = __float2bfloat16(v);
        __nv_bfloat16 lo = __float2bfloat16(v - __bfloat162float(hi));
        long b = (long)m * 384;
        g_A3[b + k] = hi;
        g_A3[b + 128 + k] = lo;
    }
}

// ---------------- bf16 wmma GEMM, BK=64, cp.async 2-stage smem pipeline ------------
// A side: logical K3 = 3*SEG, stored [hi|lo]; loader remaps k0>=2*SEG -> k0-2*SEG.
// B side: full 3-segment storage, no remap.
// EPI: 0 plain store;
//      2 accumulate(init from C) -> also write bf16 [hi|lo] to aux_bf (ctx3 layout);
//      3 relu(v + aux_f[col]) -> store to C;
//      4 plain store + fused qh epilogue (tiles with tn0>=1024 && tm0<N_DST);
//        blocks with tn0>=1024 && tm0>=N_DST early-exit.
template<int BM, int BN, int EPI, int SEG>
__global__ void wmma_gemm(const __nv_bfloat16* __restrict__ A,
                          const __nv_bfloat16* __restrict__ Bt,
                          float* __restrict__ C,
                          int K3, int lda, int ldb, int ldc,
                          long bsA, long bsB, long bsC,
                          const float* __restrict__ aux_f,
                          __nv_bfloat16* __restrict__ aux_bf)
{
    constexpr int BK = 64;
    constexpr int PAD = 8;
    constexpr int LDSH = BK + PAD;
    constexpr int CPR = BK / 8;                 // 16B chunks per row
    constexpr int FR_M = BM / 64;
    constexpr int FR_N = BN / 32;
    constexpr int A_LD = BM * CPR / 256;
    constexpr int B_LD = BN * CPR / 256;
    __shared__ __align__(16) __nv_bfloat16 sbuf[2][(BM + BN) * LDSH];
    const int bz = blockIdx.z;
    A += (long)bz * bsA; Bt += (long)bz * bsB; C += (long)bz * bsC;
    const int tid = threadIdx.x;
    const int wid = tid >> 5;
    const int wm = wid & 3;
    const int wn = wid >> 2;
    const int tm0 = blockIdx.y * BM;
    const int tn0 = blockIdx.x * BN;

    // qh columns are only consumed for rows < N_DST — skip dead blocks entirely
    if (EPI == 4 && tn0 >= 1024 && tm0 >= N_DST) return;

    wmma::fragment<wmma::accumulator, 16, 16, 16, float> cf[FR_M][FR_N];
#pragma unroll
    for (int i = 0; i < FR_M; i++)
#pragma unroll
        for (int j = 0; j < FR_N; j++) {
            if (EPI == 2)
                wmma::load_matrix_sync(cf[i][j],
                    &C[(long)(tm0 + wm * 32 + i * 16) * ldc + tn0 + wn * (BN / 2) + j * 16],
                    ldc, wmma::mem_row_major);
            else
                wmma::fill_fragment(cf[i][j], 0.f);
        }

    auto loadStage = [&](int st, int k0) {
        int ka = (k0 >= 2 * SEG) ? k0 - 2 * SEG : k0;   // A: seg2 aliases seg0
#pragma unroll
        for (int it = 0; it < A_LD; it++) {
            int idx = tid + it * 256;
            int r = idx / CPR, c8 = idx % CPR;
            cp16((unsigned int)__cvta_generic_to_shared(&sbuf[st][r * LDSH + c8 * 8]),
                 &A[(long)(tm0 + r) * lda + ka + c8 * 8]);
        }
#pragma unroll
        for (int it = 0; it < B_LD; it++) {
            int idx = tid + it * 256;
            int r = idx / CPR, c8 = idx % CPR;
            cp16((unsigned int)__cvta_generic_to_shared(&sbuf[st][(BM + r) * LDSH + c8 * 8]),
                 &Bt[(long)(tn0 + r) * ldb + k0 + c8 * 8]);
        }
        cp_commit();
    };

    const int nIter = K3 / BK;
    loadStage(0, 0);
    for (int it = 0; it < nIter; it++) {
        int st = it & 1;
        if (it + 1 < nIter) {
            loadStage(st ^ 1, (it + 1) * BK);
            cp_wait<1>();
        } else {
            cp_wait<0>();
        }
        __syncthreads();
#pragma unroll
        for (int kk = 0; kk < BK; kk += 16) {
            wmma::fragment<wmma::matrix_a, 16, 16, 16, __nv_bfloat16, wmma::row_major> af[FR_M];
            wmma::fragment<wmma::matrix_b, 16, 16, 16, __nv_bfloat16, wmma::col_major> bf[FR_N];
#pragma unroll
            for (int i = 0; i < FR_M; i++)
                wmma::load_matrix_sync(af[i], &sbuf[st][(wm * 32 + i * 16) * LDSH + kk], LDSH);
#pragma unroll
            for (int j = 0; j < FR_N; j++)
                wmma::load_matrix_sync(bf[j], &sbuf[st][(BM + wn * (BN / 2) + j * 16) * LDSH + kk], LDSH);
#pragma unroll
            for (int i = 0; i < FR_M; i++)
#pragma unroll
                for (int j = 0; j < FR_N; j++)
                    wmma::mma_sync(cf[i][j], af[i], bf[j], cf[i][j]);
        }
        __syncthreads();
    }

    if (EPI == 0 || EPI == 4) {
#pragma unroll
        for (int i = 0; i < FR_M; i++)
#pragma unroll
            for (int j = 0; j < FR_N; j++)
                wmma::store_matrix_sync(&C[(long)(tm0 + wm * 32 + i * 16) * ldc + tn0 + wn * (BN / 2) + j * 16],
                                        cf[i][j], ldc, wmma::mem_row_major);
        if (EPI == 4) {
            __syncthreads();
            if (tn0 >= 1024 && tm0 < N_DST) {
                for (int idx = tid; idx < BM * BN; idx += 256) {
                    int r = idx / BN, c = idx % BN;
                    int row = tm0 + r;
                    if (row < N_DST) {
                        int col = tn0 + c;
                        long off = (long)row * ldc + col;
                        int j = col - 1024;
                        float v = C[off] + aux_f[j];
                        C[off] = v;
                        int h = j >> 6, d = j & 63;
                        __nv_bfloat16 hi = __float2bfloat16(v);
                        __nv_bfloat16 lo = __float2bfloat16(v - __bfloat162float(hi));
                        long b = (long)row * 1536 + h * 192;
                        aux_bf[b + d] = hi;
                        aux_bf[b + 64 + d] = lo;
                    }
                }
            }
        }
    } else {
        // stage fp32 tile in shared (aliasing the dead pipeline buffers)
        float* sC = (float*)&sbuf[0][0];
        static_assert(sizeof(sbuf) >= BM * BN * sizeof(float) || EPI == 0 || EPI == 4, "sC alias too small");
#pragma unroll
        for (int i = 0; i < FR_M; i++)
#pragma unroll
            for (int j = 0; j < FR_N; j++)
                wmma::store_matrix_sync(&sC[(wm * 32 + i * 16) * BN + wn * (BN / 2) + j * 16],
                                        cf[i][j], BN, wmma::mem_row_major);
        __syncthreads();
        for (int idx = tid; idx < BM * BN; idx += 256) {
            int r = idx / BN, c = idx % BN;
            float v = sC[idx];
            int row = tm0 + r;
            if (EPI == 2) {
                int j = bz * 64 + tn0 + c;
                __nv_bfloat16 hi = __float2bfloat16(v);
                __nv_bfloat16 lo = __float2bfloat16(v - __bfloat162float(hi));
                long b = (long)row * 1536 + j;
                aux_bf[b] = hi;
                aux_bf[b + 512] = lo;
            }
            if (EPI == 3) {
                int col = tn0 + c;
                C[(long)row * ldc + col] = fmaxf(v + aux_f[col], 0.f);
            }
        }
    }
}

// ---------------- fused attention kernel: one block per dst node ----------------
// Score/ebar loops use direct ulonglong2 loads feeding fma.rn.f32x2 (no pack movs).
__global__ void attn_kernel(const float* __restrict__ ef, const float* __restrict__ dt,
                            const int* __restrict__ nidx,
                            const float* __restrict__ freq, const float* __restrict__ ph)
{
    const int n = blockIdx.x;
    const int tid = threadIdx.x;
    __shared__ __align__(16) float s_qh[512];
    __shared__ __align__(16) float s_wf[1536];
    __shared__ __align__(16) float s_te[32][132];   // row stride 528 B (16B aligned)
    __shared__ __align__(16) float s_e[32][68];     // row stride 272 B (16B aligned)
    __shared__ float s_dt[32];
    __shared__ int   s_idx[16];
    __shared__ float s_fr[128], s_ph[128];
    __shared__ float s_at[8][33];
    __shared__ float s_a2[8][17];
    __shared__ float s_ns[8][17];

    {
        const float4* qsrc = (const float4*)(g_proj + (long)n * 1536 + 1024);
        for (int i = tid; i < 128; i += 256) ((float4*)s_qh)[i] = qsrc[i];
        const float4* wsrc = (const float4*)(g_wfold + (long)n * 1536);
        for (int i = tid; i < 384; i += 256) ((float4*)s_wf)[i] = wsrc[i];
        const float4* ef4 = (const float4*)(ef + (long)n * 2048);
        for (int i = tid; i < 512; i += 256) {
            int l = i >> 4, c4 = i & 15;
            *(float4*)&s_e[l][c4 * 4] = ef4[i];
        }
    }
    if (tid < 128) { s_fr[tid] = freq[tid]; s_ph[tid] = ph[tid]; }
    if (tid < 32)  s_dt[tid] = dt[(long)n * 32 + tid];
    if (tid < 16)  s_idx[tid] = nidx[n * 16 + tid];
    __syncthreads();

    // temporal encoding via hardware cos (MUFU pipe)
    for (int i = tid; i < 4096; i += 256) {
        int l = i >> 7, d = i & 127;
        s_te[l][d] = __cosf(fmaf(s_dt[l], s_fr[d], s_ph[d]));
    }
    __syncthreads();

    const int h = tid >> 5, l = tid & 31;

    // node scores (16 distinct neighbors, coalesced), packed f32x2 math
    {
#pragma unroll
        for (int jb = 0; jb < 16; jb += 4) {
            int j = jb + (l >> 3);
            int d0 = (l & 7) * 8;
            const ulonglong2* p = (const ulonglong2*)(g_proj + (long)s_idx[j] * 1536 + h * 64 + d0);
            const ulonglong2* q = (const ulonglong2*)(s_qh + h * 64 + d0);
            unsigned long long acc = 0ull;
            ulonglong2 x0 = p[0], q0 = q[0];
            ffma2(acc, x0.x, q0.x);
            ffma2(acc, x0.y, q0.y);
            ulonglong2 x1 = p[1], q1 = q[1];
            ffma2(acc, x1.x, q1.x);
            ffma2(acc, x1.y, q1.y);
            float d0f, d1f;
            unpack2(acc, d0f, d1f);
            float d = d0f + d1f;
            d += __shfl_xor_sync(0xffffffffu, d, 1);
            d += __shfl_xor_sync(0xffffffffu, d, 2);
            d += __shfl_xor_sync(0xffffffffu, d, 4);
            if ((l & 7) == 0) s_ns[h][j] = d;
        }
        __syncwarp();
    }

    // scores + softmax (packed f32x2 dot products)
    {
        unsigned long long acc = 0ull;
        const ulonglong2* ev = (const ulonglong2*)(&s_e[l][0]);
        const ulonglong2* we = (const ulonglong2*)(s_wf + h * 192);
#pragma unroll
        for (int j = 0; j < 16; j++) {
            ulonglong2 a = ev[j], b = we[j];
            ffma2(acc, a.x, b.x);
            ffma2(acc, a.y, b.y);
        }
        const ulonglong2* tv = (const ulonglong2*)(&s_te[l][0]);
        const ulonglong2* wt = (const ulonglong2*)(s_wf + h * 192 + 64);
#pragma unroll
        for (int j = 0; j < 32; j++) {
            ulonglong2 a = tv[j], b = wt[j];
            ffma2(acc, a.x, b.x);
            ffma2(acc, a.y, b.y);
        }
        float s0, s1;
        unpack2(acc, s0, s1);
        float sc = (s_ns[h][l >> 1] + (s0 + s1)) * 0.125f;
        float mx = sc;
        for (int o = 16; o; o >>= 1) mx = fmaxf(mx, __shfl_xor_sync(0xffffffffu, mx, o));
        float ex = expf(sc - mx);
        float sm = ex;
        for (int o = 16; o; o >>= 1) sm += __shfl_xor_sync(0xffffffffu, sm, o);
        float p = ex / sm;
        s_at[h][l] = p;
        float pp = p + __shfl_xor_sync(0xffffffffu, p, 1);
        if ((l & 1) == 0) s_a2[h][l >> 1] = pp;
    }
    __syncthreads();

    // ctx node part (fp32, consumed as accumulator-init by wmma5)
    {
        int j = tid * 2;
        int hh = j >> 6;
        unsigned long long acc = 0ull;
#pragma unroll 4
        for (int r = 0; r < 16; r++) {
            unsigned long long v = *(const unsigned long long*)&g_proj[(long)s_idx[r] * 1536 + 512 + j];
            float a = s_a2[hh][r];
            ffma2(acc, pack2(a, a), v);
        }
        float o0, o1;
        unpack2(acc, o0, o1);
        *(float2*)&g_ctx[(long)n * 512 + j] = make_float2(o0, o1);
    }
    // ebar / tbar, packed loads -> bf16 [hi|lo] per head (seg2 dup not stored)
    for (int p = tid; p < 384; p += 256) {
        int hh = p / 48, c4 = (p % 48) * 4;
        unsigned long long acc0 = 0ull, acc1 = 0ull;
        if (c4 < 64) {
#pragma unroll
            for (int ll = 0; ll < 32; ll++) {
                ulonglong2 e = *(const ulonglong2*)&s_e[ll][c4];
                float a = s_at[hh][ll];
                unsigned long long a2 = pack2(a, a);
                ffma2(acc0, a2, e.x);
                ffma2(acc1, a2, e.y);
            }
        } else {
            int d = c4 - 64;
#pragma unroll
            for (int ll = 0; ll < 32; ll++) {
                ulonglong2 t4 = *(const ulonglong2*)&s_te[ll][d];
                float a = s_at[hh][ll];
                unsigned long long a2 = pack2(a, a);
                ffma2(acc0, a2, t4.x);
                ffma2(acc1, a2, t4.y);
            }
        }
        float o0, o1, o2, o3;
        unpack2(acc0, o0, o1);
        unpack2(acc1, o2, o3);
        float h0 = __bfloat162float(__float2bfloat16(o0));
        float h1 = __bfloat162float(__float2bfloat16(o1));
        float h2 = __bfloat162float(__float2bfloat16(o2));
        float h3 = __bfloat162float(__float2bfloat16(o3));
        uint2 hi4, lo4;
        hi4.x = bf2pack(o0, o1);       hi4.y = bf2pack(o2, o3);
        lo4.x = bf2pack(o0 - h0, o1 - h1);
        lo4.y = bf2pack(o2 - h2, o3 - h3);
        long base = ((long)n * 8 + hh) * 576;
        *(uint2*)&g_et3[base + c4]       = hi4;
        *(uint2*)&g_et3[base + 192 + c4] = lo4;
    }
}

// ---------------- layernorm + concat (fc epilogue fused; writes [hi|lo] hcat) -------
__global__ void ln_kernel(const float* __restrict__ lng, const float* __restrict__ lnb,
                          const float* __restrict__ nf,  const float* __restrict__ fcb)
{
    const int n = blockIdx.x, tid = threadIdx.x; // 128 threads
    float xv[3];
    int cnt = 0;
    float s = 0.f, sq = 0.f;
    for (int i = tid; i < 320; i += 128) {
        float v = g_x[(long)n * 320 + i] + fcb[i];
        if (i < 128)       v += nf[(long)n * 128 + i];
        else if (i >= 192) v += g_cosph[i - 192];
        xv[cnt++] = v;
        s += v; sq += v * v;
    }
    __shared__ float rs[4], rq[4];
    for (int o = 16; o; o >>= 1) {
        s  += __shfl_xor_sync(0xffffffffu, s,  o);
        sq += __shfl_xor_sync(0xffffffffu, sq, o);
    }
    int wid = tid >> 5, lane = tid & 31;
    if (lane == 0) { rs[wid] = s; rq[wid] = sq; }
    __syncthreads();
    float ts = rs[0] + rs[1] + rs[2] + rs[3];
    float tq = rq[0] + rq[1] + rq[2] + rq[3];
    float mu = ts * (1.f / 320.f);
    float var = tq * (1.f / 320.f) - mu * mu;
    float inv = rsqrtf(var + 1e-5f);
    long b = (long)n * 1344;
    cnt = 0;
    for (int i = tid; i < 320; i += 128) {
        float w = lng[i] * (xv[cnt++] - mu) * inv + lnb[i];
        int c = 128 + i;
        __nv_bfloat16 hi = __float2bfloat16(w);
        __nv_bfloat16 lo = __float2bfloat16(w - __bfloat162float(hi));
        g_hcat3[b + c] = hi;
        g_hcat3[b + 448 + c] = lo;
    }
    {
        float w = nf[(long)n * 128 + tid];
        __nv_bfloat16 hi = __float2bfloat16(w);
        __nv_bfloat16 lo = __float2bfloat16(w - __bfloat162float(hi));
        g_hcat3[b + tid] = hi;
        g_hcat3[b + 448 + tid] = lo;
    }
}

// ---------------- launch ----------------
extern "C" void kernel_launch(void* const* d_in, const int* in_sizes, int n_in,
                              void* d_out, int out_size) {
    const float* nf   = (const float*)d_in[0];
    const float* ef   = (const float*)d_in[1];
    const float* dt   = (const float*)d_in[2];
    const int*   nidx = (const int*)  d_in[3];
    const float* freq = (const float*)d_in[4];
    const float* ph   = (const float*)d_in[5];
    const float* wqs  = (const float*)d_in[6];
    const float* wks  = (const float*)d_in[7];
    const float* wvs  = (const float*)d_in[8];
    const float* fcw  = (const float*)d_in[9];
    const float* fcb  = (const float*)d_in[10];
    const float* lng  = (const float*)d_in[11];
    const float* lnb  = (const float*)d_in[12];
    const float* nw   = (const float*)d_in[13];
    const float* nb   = (const float*)d_in[14];
    float* out = (float*)d_out;

    float *p_proj, *p_wfold, *p_ctx, *p_x, *p_biasq;
    __nv_bfloat16 *p_A3, *p_B3, *p_qh3, *p_wk3, *p_et3, *p_wv3, *p_ctx3, *p_fcw3, *p_hcat3, *p_nodew3;
    cudaGetSymbolAddress((void**)&p_proj,   g_proj);
    cudaGetSymbolAddress((void**)&p_wfold,  g_wfold);
    cudaGetSymbolAddress((void**)&p_ctx,    g_ctx);
    cudaGetSymbolAddress((void**)&p_x,      g_x);
    cudaGetSymbolAddress((void**)&p_biasq,  g_biasq);
    cudaGetSymbolAddress((void**)&p_A3,     g_A3);
    cudaGetSymbolAddress((void**)&p_B3,     g_B3);
    cudaGetSymbolAddress((void**)&p_qh3,    g_qh3);
    cudaGetSymbolAddress((void**)&p_wk3,    g_wk3);
    cudaGetSymbolAddress((void**)&p_et3,    g_et3);
    cudaGetSymbolAddress((void**)&p_wv3,    g_wv3);
    cudaGetSymbolAddress((void**)&p_ctx3,   g_ctx3);
    cudaGetSymbolAddress((void**)&p_fcw3,   g_fcw3);
    cudaGetSymbolAddress((void**)&p_hcat3,  g_hcat3);
    cudaGetSymbolAddress((void**)&p_nodew3, g_nodew3);

    // 1) weight splits + biasq + cosph + A3 input split (merged)
    const int PREP_TOTAL = 1843840 + N_SRC * 128;
    prep_kernel<<<(PREP_TOTAL + 255) / 256, 256>>>(wks, wvs, wqs, fcw, nw, ph, nf);

    // 2) node_k|node_v|qh projection (tensor), qh-bias + qh3 split fused;
    //    dead qh blocks early-exit; A seg2 remapped
    wmma_gemm<128,128,4,128><<<dim3(12, 128), 256>>>(p_A3, p_B3, p_proj, 384, 384, 384, 1536,
                                                     0, 0, 0, p_biasq, p_qh3);

    // 3) fold q into K-weights (tensor, batched per head)
    wmma_gemm<128,64,0,64><<<dim3(3, 64, 8), 256>>>(p_qh3, p_wk3, p_wfold, 192, 1536, 192, 1536,
                                                    192, (long)192 * 192, 192, nullptr, nullptr);

    // 4) fused attention per dst (writes g_ctx fp32 + g_et3 [hi|lo])
    attn_kernel<<<N_DST, 256>>>(ef, dt, nidx, freq, ph);

    // 5) V projection (tensor, batched, accumulate onto ctx, emit ctx3 [hi|lo])
    wmma_gemm<128,64,2,192><<<dim3(1, 64, 8), 256>>>(p_et3, p_wv3, p_ctx, 576, 4608, 576, 512,
                                                     576, (long)64 * 576, 64, nullptr, p_ctx3);

    // 6) fc (tensor): 8192x320, K'=1536; epilogue fused in ln
    wmma_gemm<128,64,0,512><<<dim3(5, 64), 256>>>(p_ctx3, p_fcw3, p_x, 1536, 1536, 1536, 320,
                                                  0, 0, 0, nullptr, nullptr);

    // 7) layernorm + concat (writes [hi|lo] hcat)
    ln_kernel<<<N_DST, 128>>>(lng, lnb, nf, fcb);

    // 8) final (tensor), bias+relu fused, writes out directly
    wmma_gemm<128,64,3,448><<<dim3(2, 64), 256>>>(p_hcat3, p_nodew3, out, 1344, 1344, 1344, 128,
                                                  0, 0, 0, nb, nullptr);
}